// round 1
// baseline (speedup 1.0000x reference)
#include <cuda_runtime.h>
#include <math.h>

// ---------------- problem constants ----------------
namespace {
constexpr int    Nv   = 4096;
constexpr int    Din  = 128;
constexpr int    Dh   = 256;
constexpr int    Kp   = 17;          // K+1
constexpr float  Eps  = 1e-8f;
constexpr float  InvT = 5.0f;        // 1/TEMP
constexpr size_t NN   = (size_t)Nv * (size_t)Nv;

// scratch heap layout (units: floats)
constexpr size_t O_SIM  = 0;                           // N*N  (sim, later S)
constexpr size_t O_W    = O_SIM + NN;                  // N*N  (A -> Wund in place)
constexpr size_t O_CNT  = O_W + NN;                    // N*N  (cnt)
constexpr size_t O_X1   = O_CNT + NN;                  // N*Din
constexpr size_t O_AGG  = O_X1 + (size_t)Nv*Din;       // N*Din
constexpr size_t O_HN   = O_AGG + (size_t)Nv*Din;      // N*Dh
constexpr size_t O_XW1  = O_HN + (size_t)Nv*Dh;
constexpr size_t O_BUFA = O_XW1 + (size_t)Nv*Dh;
constexpr size_t O_BUFB = O_BUFA + (size_t)Nv*Dh;
constexpr size_t O_H1   = O_BUFB + (size_t)Nv*Dh;
constexpr size_t O_G1   = O_H1 + (size_t)Nv*Dh;
constexpr size_t O_Z1   = O_G1 + (size_t)Nv*Dh;
constexpr size_t O_Z2   = O_Z1 + (size_t)Nv*Dh;
constexpr size_t O_DEG  = O_Z2 + (size_t)Nv*Dh;
constexpr size_t O_DINV = O_DEG + Nv;
constexpr size_t O_M    = O_DINV + Nv;
constexpr size_t O_SS   = O_M + Nv;
constexpr size_t O_DIAG = O_SS + Nv;
constexpr size_t O_PF   = O_DIAG + Nv;
constexpr size_t O_PB   = O_PF + Nv;
constexpr size_t O_TOPI = O_PB + Nv;                   // N*Kp ints (stored in floats)
constexpr size_t O_TOPV = O_TOPI + (size_t)Nv*Kp;      // N*Kp floats
constexpr size_t TOTAL  = O_TOPV + (size_t)Nv*Kp;
}

__device__ __align__(256) float g_heap[TOTAL];

// ---------------- small utility kernels ----------------
__global__ void zero_k(float* p, size_t n) {
    size_t i = (size_t)blockIdx.x * blockDim.x + threadIdx.x;
    size_t stride = (size_t)gridDim.x * blockDim.x;
    for (; i < n; i += stride) p[i] = 0.f;
}

__global__ void deg_init_k(float* deg) {
    int i = blockIdx.x * blockDim.x + threadIdx.x;
    if (i < Nv) deg[i] = 1.f;                 // self loop
}

__global__ void deg_count_k(const int* dst, float* deg, int E) {
    int e = blockIdx.x * blockDim.x + threadIdx.x;
    if (e < E) atomicAdd(&deg[dst[e]], 1.f);
}

__global__ void dinv_k(const float* deg, float* dinv) {
    int i = blockIdx.x * blockDim.x + threadIdx.x;
    if (i < Nv) dinv[i] = rsqrtf(deg[i]);     // deg >= 1 always
}

__global__ void x1_k(const float* x, const float* pf, const float* ps, float* x1) {
    int i = blockIdx.x * blockDim.x + threadIdx.x;
    if (i >= Nv * Din) return;
    int c = i % Din;
    float v = x[i] * pf[c];
    x1[i] = fmaxf(v, 0.f) * ps[c];
}

template<int F>
__global__ void self_init_k(const float* X, const float* dinv, float* out) {
    int i = blockIdx.x * blockDim.x + threadIdx.x;
    if (i >= Nv * F) return;
    int r = i / F;
    float dv = dinv[r];
    out[i] = dv * dv * X[i];
}

template<int F>
__global__ void edge_scatter_k(const float* X, const int* es, const int* ed,
                               const float* dinv, float* out) {
    int e = blockIdx.x;
    int c = threadIdx.x;
    int s = es[e], d = ed[e];
    float w = dinv[s] * dinv[d];
    atomicAdd(&out[(size_t)d * F + c], w * X[(size_t)s * F + c]);
}

// h = [x1, agg] * p_balance ; hn = h / (||h|| + eps)
__global__ void hn_k(const float* x1, const float* agg, const float* pbal, float* hn) {
    __shared__ float sh[256];
    int r = blockIdx.x, t = threadIdx.x;
    float v = (t < Din ? x1[(size_t)r * Din + t] : agg[(size_t)r * Din + (t - Din)]) * pbal[t];
    sh[t] = v * v; __syncthreads();
    for (int s = 128; s > 0; s >>= 1) { if (t < s) sh[t] += sh[t + s]; __syncthreads(); }
    float nrm = sqrtf(sh[0]);
    hn[(size_t)r * Dh + t] = v / (nrm + Eps);
}

// ---------------- SGEMM (fp32, tiled) ----------------
// NT: C[M,Nn] = A[M,K] * B[Nn,K]^T ; else C = A[M,K] * B[K,Nn]. All row-major.
template<int BM, int BN, int BK, int TM, int TN, bool NT>
__global__ void sgemm_k(const float* A, const float* B, float* C,
                        int M, int Nc, int Kk) {
    __shared__ float As[BK][BM];
    __shared__ float Bs[BK][BN];
    constexpr int THREADS = (BM / TM) * (BN / TN);
    int tid = threadIdx.x;
    int brow = blockIdx.y * BM, bcol = blockIdx.x * BN;
    int tx = tid % (BN / TN);
    int ty = tid / (BN / TN);
    float acc[TM][TN] = {};
    float ra[TM], rb[TN];

    for (int k0 = 0; k0 < Kk; k0 += BK) {
        // load A tile (transpose into As[k][m])
        constexpr int ALD = BM * BK / THREADS / 4;
        #pragma unroll
        for (int l = 0; l < ALD; l++) {
            int li = tid + l * THREADS;
            int m = li / (BK / 4);
            int kq = li % (BK / 4);
            float4 v = *(const float4*)(A + (size_t)(brow + m) * Kk + k0 + kq * 4);
            As[kq * 4 + 0][m] = v.x; As[kq * 4 + 1][m] = v.y;
            As[kq * 4 + 2][m] = v.z; As[kq * 4 + 3][m] = v.w;
        }
        // load B tile
        constexpr int BLD = BN * BK / THREADS / 4;
        if (NT) {
            #pragma unroll
            for (int l = 0; l < BLD; l++) {
                int li = tid + l * THREADS;
                int n = li / (BK / 4);
                int kq = li % (BK / 4);
                float4 v = *(const float4*)(B + (size_t)(bcol + n) * Kk + k0 + kq * 4);
                Bs[kq * 4 + 0][n] = v.x; Bs[kq * 4 + 1][n] = v.y;
                Bs[kq * 4 + 2][n] = v.z; Bs[kq * 4 + 3][n] = v.w;
            }
        } else {
            #pragma unroll
            for (int l = 0; l < BLD; l++) {
                int li = tid + l * THREADS;
                int kk = li / (BN / 4);
                int nq = li % (BN / 4);
                float4 v = *(const float4*)(B + (size_t)(k0 + kk) * Nc + bcol + nq * 4);
                *(float4*)&Bs[kk][nq * 4] = v;
            }
        }
        __syncthreads();
        #pragma unroll
        for (int kk = 0; kk < BK; kk++) {
            #pragma unroll
            for (int i = 0; i < TM; i++) ra[i] = As[kk][ty * TM + i];
            #pragma unroll
            for (int j = 0; j < TN; j++) rb[j] = Bs[kk][tx * TN + j];
            #pragma unroll
            for (int i = 0; i < TM; i++)
                #pragma unroll
                for (int j = 0; j < TN; j++) acc[i][j] += ra[i] * rb[j];
        }
        __syncthreads();
    }
    #pragma unroll
    for (int i = 0; i < TM; i++)
        #pragma unroll
        for (int j = 0; j < TN; j += 4) {
            float4 v = make_float4(acc[i][j], acc[i][j+1], acc[i][j+2], acc[i][j+3]);
            *(float4*)(C + (size_t)(brow + ty * TM + i) * Nc + bcol + tx * TN + j) = v;
        }
}

// ---------------- top-k (iterative argmax, tie -> lowest index) ----------------
__global__ void topk_k(const float* sim, int* topi, float* topv) {
    __shared__ float sv[Nv];
    __shared__ float bv[256];
    __shared__ int   bi[256];
    int r = blockIdx.x, t = threadIdx.x;
    for (int i = t; i < Nv; i += 256) sv[i] = sim[(size_t)r * Nv + i];
    __syncthreads();
    for (int k = 0; k < Kp; k++) {
        float best = -1e30f; int besti = Nv;
        for (int i = t; i < Nv; i += 256) {
            float v = sv[i];
            if (v > best || (v == best && i < besti)) { best = v; besti = i; }
        }
        bv[t] = best; bi[t] = besti; __syncthreads();
        for (int s = 128; s > 0; s >>= 1) {
            if (t < s) {
                if (bv[t + s] > bv[t] || (bv[t + s] == bv[t] && bi[t + s] < bi[t])) {
                    bv[t] = bv[t + s]; bi[t] = bi[t + s];
                }
            }
            __syncthreads();
        }
        if (t == 0) {
            topv[r * Kp + k] = bv[0];
            topi[r * Kp + k] = bi[0];
            sv[bi[0]] = -1e30f;
        }
        __syncthreads();
    }
}

__global__ void scatterA_k(const int* ti, const float* tv, float* A, float* C) {
    int i = blockIdx.x * blockDim.x + threadIdx.x;
    if (i >= Nv * Kp) return;
    int r = i / Kp;
    int c = ti[i];
    float v = tv[i];
    if (v != v) v = 0.f;   // nan_to_num
    atomicAdd(&A[(size_t)r * Nv + c], v);
    atomicAdd(&C[(size_t)r * Nv + c], 1.f);
}

// Wund = relu(where(cnt>0, (A+A^T)/max(cnt,1), 0)), symmetric, in place
__global__ void wund_k(float* A, const float* C) {
    size_t idx = (size_t)blockIdx.x * blockDim.x + threadIdx.x;
    if (idx >= NN) return;
    int i = (int)(idx / Nv), j = (int)(idx % Nv);
    if (j < i) return;
    float a = A[(size_t)i * Nv + j] + A[(size_t)j * Nv + i];
    float c = C[(size_t)i * Nv + j] + C[(size_t)j * Nv + i];
    float o = (c > 0.f) ? fmaxf(a / fmaxf(c, 1.f), 0.f) : 0.f;
    A[(size_t)i * Nv + j] = o;
    A[(size_t)j * Nv + i] = o;
}

__global__ void bias_relu_k(const float* in, const float* b, float* out) {
    int i = blockIdx.x * blockDim.x + threadIdx.x;
    if (i >= Nv * Dh) return;
    out[i] = fmaxf(in[i] + b[i % Dh], 0.f);
}

// z = elu(in + b); out = z / (||z|| + eps)  (row-wise)
__global__ void elu_norm_k(const float* in, const float* b, float* out) {
    __shared__ float sh[256];
    int r = blockIdx.x, t = threadIdx.x;
    float v = in[(size_t)r * Dh + t] + b[t];
    v = v > 0.f ? v : expm1f(v);
    sh[t] = v * v; __syncthreads();
    for (int s = 128; s > 0; s >>= 1) { if (t < s) sh[t] += sh[t + s]; __syncthreads(); }
    out[(size_t)r * Dh + t] = v / (sqrtf(sh[0]) + Eps);
}

// out[row,:] = sum_j W[row,j] * X[j,:] exploiting ~34 nnz/row of Wund
__global__ void spmm_scan_k(const float* W, const float* X, float* out) {
    __shared__ int   si[256];
    __shared__ float sw[256];
    __shared__ int   scnt;
    int r = blockIdx.x, t = threadIdx.x;
    const float* wr = W + (size_t)r * Nv;
    float acc = 0.f;
    for (int base = 0; base < Nv; base += 256) {
        if (t == 0) scnt = 0;
        __syncthreads();
        float w = wr[base + t];
        if (w != 0.f) { int p = atomicAdd(&scnt, 1); si[p] = base + t; sw[p] = w; }
        __syncthreads();
        int c = scnt;
        for (int q = 0; q < c; q++) acc += sw[q] * X[(size_t)si[q] * Dh + t];
        __syncthreads();
    }
    out[(size_t)r * Dh + t] = acc;
}

// per-row softmax stats over S*InvT; also diag(prob)
__global__ void softmax_stats_k(const float* S, float* gm, float* gs, float* gdiag) {
    __shared__ float sh[256];
    int r = blockIdx.x, t = threadIdx.x;
    const float* row = S + (size_t)r * Nv;
    float mx = -1e30f;
    for (int j = t; j < Nv; j += 256) mx = fmaxf(mx, row[j] * InvT);
    sh[t] = mx; __syncthreads();
    for (int s = 128; s > 0; s >>= 1) { if (t < s) sh[t] = fmaxf(sh[t], sh[t + s]); __syncthreads(); }
    float m = sh[0];
    __syncthreads();
    float sum = 0.f;
    for (int j = t; j < Nv; j += 256) sum += expf(row[j] * InvT - m);
    sh[t] = sum; __syncthreads();
    for (int s = 128; s > 0; s >>= 1) { if (t < s) sh[t] += sh[t + s]; __syncthreads(); }
    if (t == 0) {
        gm[r] = m; gs[r] = sh[0];
        gdiag[r] = expf(row[r] * InvT - m) / sh[0];
    }
}

// pf[r] = sum_j prob[r,j]*W[r,j]; pb[j] += prob[r,j]*W[r,j]  (W symmetric)
__global__ void pfpb_k(const float* S, const float* W, const float* gm, const float* gs,
                       float* pf, float* pb) {
    __shared__ float sh[256];
    int r = blockIdx.x, t = threadIdx.x;
    float m = gm[r], s = gs[r];
    const float* srow = S + (size_t)r * Nv;
    const float* wrow = W + (size_t)r * Nv;
    float acc = 0.f;
    for (int j = t; j < Nv; j += 256) {
        float w = wrow[j];
        if (w > 0.f) {
            float q = expf(srow[j] * InvT - m) / s * w;
            acc += q;
            atomicAdd(&pb[j], q);
        }
    }
    sh[t] = acc; __syncthreads();
    for (int st = 128; st > 0; st >>= 1) { if (t < st) sh[t] += sh[t + st]; __syncthreads(); }
    if (t == 0) pf[r] = sh[0];
}

__global__ void loss_k(const float* diag, const float* pf, const float* pb, float* out) {
    __shared__ float s1[256], s2[256], s3[256];
    int t = threadIdx.x;
    float a = 0.f, b = 0.f, c = 0.f;
    for (int i = t; i < Nv; i += 256) {
        a -= logf(fmaxf(diag[i], Eps));
        b -= logf(fmaxf(pf[i], Eps));
        c -= logf(fmaxf(pb[i], Eps));
    }
    s1[t] = a; s2[t] = b; s3[t] = c; __syncthreads();
    for (int st = 128; st > 0; st >>= 1) {
        if (t < st) { s1[t] += s1[t + st]; s2[t] += s2[t + st]; s3[t] += s3[t + st]; }
        __syncthreads();
    }
    if (t == 0) out[0] = s1[0] / Nv + 0.5f * (s2[0] / Nv + s3[0] / Nv);
}

// ---------------- host launcher ----------------
extern "C" void kernel_launch(void* const* d_in, const int* in_sizes, int n_in,
                              void* d_out, int out_size) {
    const float* x       = (const float*)d_in[0];
    const int*   esrc    = (const int*)d_in[1];
    const int*   edst    = (const int*)d_in[2];
    const float* p_feat  = (const float*)d_in[3];
    const float* p_share = (const float*)d_in[4];
    const float* p_bal   = (const float*)d_in[5];
    const float* W1      = (const float*)d_in[6];
    const float* b1      = (const float*)d_in[7];
    const float* W2      = (const float*)d_in[8];
    const float* b2      = (const float*)d_in[9];
    float* out = (float*)d_out;
    int E = in_sizes[1];

    float* H = nullptr;
    cudaGetSymbolAddress((void**)&H, g_heap);
    float* sim  = H + O_SIM;  float* W    = H + O_W;    float* cnt  = H + O_CNT;
    float* x1   = H + O_X1;   float* agg  = H + O_AGG;  float* hn   = H + O_HN;
    float* xw1  = H + O_XW1;  float* bufA = H + O_BUFA; float* bufB = H + O_BUFB;
    float* h1   = H + O_H1;   float* g1   = H + O_G1;   float* z1   = H + O_Z1;
    float* z2   = H + O_Z2;   float* deg  = H + O_DEG;  float* dinv = H + O_DINV;
    float* gm   = H + O_M;    float* gs   = H + O_SS;   float* gdiag= H + O_DIAG;
    float* pf   = H + O_PF;   float* pb   = H + O_PB;
    int*   topi = (int*)(H + O_TOPI);
    float* topv = H + O_TOPV;

    // GCN normalization weights
    deg_init_k<<<(Nv + 255) / 256, 256>>>(deg);
    deg_count_k<<<(E + 255) / 256, 256>>>(edst, deg, E);
    dinv_k<<<(Nv + 255) / 256, 256>>>(deg, dinv);

    // prompted features
    x1_k<<<(Nv * Din) / 256, 256>>>(x, p_feat, p_share, x1);

    // agg = A_norm @ x1   (self loop init + edge scatter)
    self_init_k<Din><<<(Nv * Din) / 256, 256>>>(x1, dinv, agg);
    edge_scatter_k<Din><<<E, Din>>>(x1, esrc, edst, dinv, agg);

    // hn = normalize([x1, agg] * p_balance)
    hn_k<<<Nv, 256>>>(x1, agg, p_bal, hn);

    // sim = hn @ hn^T
    sgemm_k<128,128,16,8,8,true><<<dim3(Nv/128, Nv/128), 256>>>(hn, hn, sim, Nv, Nv, Dh);

    // top-(K+1) per row
    topk_k<<<Nv, 256>>>(sim, topi, topv);

    // build symmetric reconstructed adjacency Wund
    zero_k<<<4096, 256>>>(W, NN);
    zero_k<<<4096, 256>>>(cnt, NN);
    scatterA_k<<<(Nv * Kp + 255) / 256, 256>>>(topi, topv, W, cnt);
    wund_k<<<(int)(NN / 256), 256>>>(W, cnt);

    // xw1 = x1 @ W1
    sgemm_k<64,64,16,4,4,false><<<dim3(Dh/64, Nv/64), 256>>>(x1, W1, xw1, Nv, Dh, Din);

    // view 1: sparse GCN
    self_init_k<Dh><<<(Nv * Dh) / 256, 256>>>(xw1, dinv, bufA);
    edge_scatter_k<Dh><<<E, Dh>>>(xw1, esrc, edst, dinv, bufA);
    bias_relu_k<<<(Nv * Dh) / 256, 256>>>(bufA, b1, h1);
    sgemm_k<64,64,16,4,4,false><<<dim3(Dh/64, Nv/64), 256>>>(h1, W2, bufB, Nv, Dh, Dh);
    self_init_k<Dh><<<(Nv * Dh) / 256, 256>>>(bufB, dinv, bufA);
    edge_scatter_k<Dh><<<E, Dh>>>(bufB, esrc, edst, dinv, bufA);
    elu_norm_k<<<Nv, 256>>>(bufA, b2, z1);   // z1 normalized

    // view 2: reconstructed (sparse-in-practice) dense graph
    spmm_scan_k<<<Nv, 256>>>(W, xw1, bufA);
    bias_relu_k<<<(Nv * Dh) / 256, 256>>>(bufA, b1, g1);
    sgemm_k<64,64,16,4,4,false><<<dim3(Dh/64, Nv/64), 256>>>(g1, W2, bufB, Nv, Dh, Dh);
    spmm_scan_k<<<Nv, 256>>>(W, bufB, bufA);
    elu_norm_k<<<Nv, 256>>>(bufA, b2, z2);   // z2 normalized

    // S = z1n @ z2n^T (unscaled; InvT applied in softmax)
    sgemm_k<128,128,16,8,8,true><<<dim3(Nv/128, Nv/128), 256>>>(z1, z2, sim, Nv, Nv, Dh);

    // softmax stats + losses
    softmax_stats_k<<<Nv, 256>>>(sim, gm, gs, gdiag);
    zero_k<<<16, 256>>>(pb, (size_t)Nv);
    pfpb_k<<<Nv, 256>>>(sim, W, gm, gs, pf, pb);
    loss_k<<<1, 256>>>(gdiag, pf, pb, out);
}

// round 2
// speedup vs baseline: 1.2517x; 1.2517x over previous
#include <cuda_runtime.h>
#include <math.h>

// ---------------- problem constants ----------------
namespace {
constexpr int    Nv   = 4096;
constexpr int    Din  = 128;
constexpr int    Dh   = 256;
constexpr int    Kp   = 17;          // K+1
constexpr float  Eps  = 1e-8f;
constexpr float  InvT = 5.0f;        // 1/TEMP
constexpr size_t NN   = (size_t)Nv * (size_t)Nv;
constexpr int    Emax = 131072;
constexpr int    COO_CAP = 131072;

// scratch heap layout (units: floats)
constexpr size_t O_SIM  = 0;                            // N*N
constexpr size_t O_W    = O_SIM + NN;                   // N*N (encoded A -> Wund)
constexpr size_t O_X1   = O_W + NN;
constexpr size_t O_AGG  = O_X1  + (size_t)Nv*Din;
constexpr size_t O_HN   = O_AGG + (size_t)Nv*Din;
constexpr size_t O_XW1  = O_HN  + (size_t)Nv*Dh;
constexpr size_t O_BUFA = O_XW1 + (size_t)Nv*Dh;
constexpr size_t O_BUFB = O_BUFA+ (size_t)Nv*Dh;
constexpr size_t O_Z1   = O_BUFB+ (size_t)Nv*Dh;
constexpr size_t O_Z2   = O_Z1  + (size_t)Nv*Dh;
constexpr size_t O_DEG  = O_Z2  + (size_t)Nv*Dh;
constexpr size_t O_DINV = O_DEG + Nv;
constexpr size_t O_GS   = O_DINV+ Nv;                   // gs, pf, pb contiguous (one zero)
constexpr size_t O_PF   = O_GS  + Nv;
constexpr size_t O_PB   = O_PF  + Nv;
constexpr size_t O_GD   = O_PB  + Nv;
constexpr size_t O_RPTR = O_GD  + Nv;                   // Nv+1 ints
constexpr size_t O_FILL = O_RPTR+ (Nv + 4);
constexpr size_t O_CSRC = O_FILL+ Nv;                   // Emax ints
constexpr size_t O_TOPI = O_CSRC+ Emax;                 // Nv*Kp ints
constexpr size_t O_TOPV = O_TOPI+ (size_t)Nv*Kp;
constexpr size_t O_COOI = O_TOPV+ (size_t)Nv*Kp;
constexpr size_t O_COOJ = O_COOI+ COO_CAP;
constexpr size_t O_COOW = O_COOJ+ COO_CAP;
constexpr size_t O_NNZ  = O_COOW+ COO_CAP;
constexpr size_t TOTAL  = O_NNZ + 4;
}

__device__ __align__(256) float g_heap[TOTAL];

// ---------------- fast exp (FMA only, |x| <= ~8) ----------------
__device__ __forceinline__ float fexp(float x) {
    float t  = x * 1.4426950408889634f;
    float rf = __fadd_rn(t, 12582912.0f);             // round-to-nearest int
    int   e  = __float_as_int(rf) - 0x4B400000;
    float r  = __fadd_rn(rf, -12582912.0f);
    float f  = t - r;                                  // f in [-0.5, 0.5]
    float p  = fmaf(1.5403530394e-4f, f, 1.3333558146e-3f);
    p = fmaf(p, f, 9.6181291076e-3f);
    p = fmaf(p, f, 5.5504108665e-2f);
    p = fmaf(p, f, 2.4022650696e-1f);
    p = fmaf(p, f, 6.9314718056e-1f);
    p = fmaf(p, f, 1.0f);
    return __int_as_float(__float_as_int(p) + (e << 23));
}

// ---------------- small utility kernels ----------------
__global__ void zero_k(float* p, size_t n) {
    size_t i = (size_t)blockIdx.x * blockDim.x + threadIdx.x;
    size_t stride = (size_t)gridDim.x * blockDim.x;
    for (; i < n; i += stride) p[i] = 0.f;
}
__global__ void zero_i_k(int* p) { p[0] = 0; }

__global__ void deg_init_k(float* deg) {
    int i = blockIdx.x * blockDim.x + threadIdx.x;
    if (i < Nv) deg[i] = 1.f;                 // self loop
}
__global__ void deg_count_k(const int* dst, float* deg, int E) {
    int e = blockIdx.x * blockDim.x + threadIdx.x;
    if (e < E) atomicAdd(&deg[dst[e]], 1.f);
}
__global__ void dinv_k(const float* deg, float* dinv) {
    int i = blockIdx.x * blockDim.x + threadIdx.x;
    if (i < Nv) dinv[i] = rsqrtf(deg[i]);
}

__global__ void x1_k(const float* x, const float* pf, const float* ps, float* x1) {
    int i = blockIdx.x * blockDim.x + threadIdx.x;
    if (i >= Nv * Din) return;
    int c = i % Din;
    float v = x[i] * pf[c];
    x1[i] = fmaxf(v, 0.f) * ps[c];
}

// ---------------- CSR build ----------------
// rowptr via single-block scan of integer degrees (deg includes the self loop)
__global__ void scan_k(const float* deg, int* rowptr, int* fill) {
    __shared__ int s[1024];
    int t = threadIdx.x;
    int c[4]; int loc = 0;
    #pragma unroll
    for (int q = 0; q < 4; q++) { c[q] = (int)deg[t * 4 + q] - 1; loc += c[q]; }
    s[t] = loc; __syncthreads();
    for (int off = 1; off < 1024; off <<= 1) {
        int v = (t >= off) ? s[t - off] : 0;
        __syncthreads();
        s[t] += v;
        __syncthreads();
    }
    int run = s[t] - loc;
    #pragma unroll
    for (int q = 0; q < 4; q++) {
        rowptr[t * 4 + q] = run; run += c[q];
        fill[t * 4 + q] = 0;
    }
    if (t == 1023) rowptr[Nv] = run;
}

__global__ void fill_k(const int* es, const int* ed, const int* rowptr,
                       int* fill, int* csrc, int E) {
    int e = blockIdx.x * blockDim.x + threadIdx.x;
    if (e >= E) return;
    int d = ed[e];
    int p = rowptr[d] + atomicAdd(&fill[d], 1);
    csrc[p] = es[e];
}

// ---------------- CSR gather propagate (atomic-free) ----------------
// EPI: 0 none, 1 relu(v+bias), 2 elu(v+bias) + row L2-normalize (F must be 256)
template<int F, int EPI>
__global__ void prop_k(const float* __restrict__ X, const int* __restrict__ rowptr,
                       const int* __restrict__ csrc, const float* __restrict__ dinv,
                       const float* __restrict__ bias, float* __restrict__ out) {
    __shared__ int   sI[F];
    __shared__ float sW[F];
    __shared__ float red[(EPI == 2) ? F : 1];
    int r = blockIdx.x, t = threadIdx.x;
    int beg = rowptr[r], end = rowptr[r + 1];
    float acc = 0.f;
    for (int base = beg; base < end; base += F) {
        int m = min(F, end - base);
        if (t < m) { int s = csrc[base + t]; sI[t] = s; sW[t] = dinv[s]; }
        __syncthreads();
        #pragma unroll 4
        for (int q = 0; q < m; q++) acc += sW[q] * X[(size_t)sI[q] * F + t];
        __syncthreads();
    }
    float dv = dinv[r];
    float v = dv * dv * X[(size_t)r * F + t] + dv * acc;
    if (EPI == 0) {
        out[(size_t)r * F + t] = v;
    } else if (EPI == 1) {
        out[(size_t)r * F + t] = fmaxf(v + bias[t], 0.f);
    } else {
        v += bias[t];
        v = v > 0.f ? v : expm1f(v);
        red[t] = v * v; __syncthreads();
        for (int s = F / 2; s > 0; s >>= 1) { if (t < s) red[t] += red[t + s]; __syncthreads(); }
        out[(size_t)r * F + t] = v / (sqrtf(red[0]) + Eps);
    }
}

// h = [x1, agg] * p_balance ; hn = h / (||h|| + eps)
__global__ void hn_k(const float* x1, const float* agg, const float* pbal, float* hn) {
    __shared__ float sh[256];
    int r = blockIdx.x, t = threadIdx.x;
    float v = (t < Din ? x1[(size_t)r * Din + t] : agg[(size_t)r * Din + (t - Din)]) * pbal[t];
    sh[t] = v * v; __syncthreads();
    for (int s = 128; s > 0; s >>= 1) { if (t < s) sh[t] += sh[t + s]; __syncthreads(); }
    float nrm = sqrtf(sh[0]);
    hn[(size_t)r * Dh + t] = v / (nrm + Eps);
}

// ---------------- big NT GEMM with packed f32x2 FMA ----------------
__device__ __forceinline__ unsigned long long dup2(float v) {
    unsigned long long b = (unsigned long long)__float_as_uint(v);
    return b | (b << 32);
}

// C[4096,4096] = A[4096,K] * B[4096,K]^T ; FUSE: no C write, instead
// gs[r] += sum_j fexp(5*c_rj), gdiag[r] = fexp(5*c_rr).
template<bool FUSE>
__global__ __launch_bounds__(256, 2)
void fgemm_nt_k(const float* __restrict__ A, const float* __restrict__ B,
                float* __restrict__ C, float* __restrict__ gs,
                float* __restrict__ gdiag, int Kk) {
    __shared__ unsigned long long As2[16][128];   // A values duplicated (v,v)
    __shared__ float Bs[16][128];
    __shared__ float rowsum[128];
    int tid = threadIdx.x;
    int brow = blockIdx.y * 128, bcol = blockIdx.x * 128;
    int tx = tid % 16, ty = tid / 16;

    unsigned long long acc[8][4];
    #pragma unroll
    for (int i = 0; i < 8; i++)
        #pragma unroll
        for (int j = 0; j < 4; j++) acc[i][j] = 0ULL;

    for (int k0 = 0; k0 < Kk; k0 += 16) {
        #pragma unroll
        for (int l = 0; l < 2; l++) {
            int li = tid + l * 256;
            int m = li >> 2, kq = li & 3;
            float4 va = *(const float4*)(A + (size_t)(brow + m) * Kk + k0 + kq * 4);
            As2[kq * 4 + 0][m] = dup2(va.x);
            As2[kq * 4 + 1][m] = dup2(va.y);
            As2[kq * 4 + 2][m] = dup2(va.z);
            As2[kq * 4 + 3][m] = dup2(va.w);
            float4 vb = *(const float4*)(B + (size_t)(bcol + m) * Kk + k0 + kq * 4);
            Bs[kq * 4 + 0][m] = vb.x;
            Bs[kq * 4 + 1][m] = vb.y;
            Bs[kq * 4 + 2][m] = vb.z;
            Bs[kq * 4 + 3][m] = vb.w;
        }
        __syncthreads();
        #pragma unroll
        for (int kk = 0; kk < 16; kk++) {
            ulonglong2 a0 = *(const ulonglong2*)&As2[kk][ty * 8 + 0];
            ulonglong2 a1 = *(const ulonglong2*)&As2[kk][ty * 8 + 2];
            ulonglong2 a2 = *(const ulonglong2*)&As2[kk][ty * 8 + 4];
            ulonglong2 a3 = *(const ulonglong2*)&As2[kk][ty * 8 + 6];
            ulonglong2 b0 = *(const ulonglong2*)&Bs[kk][tx * 8 + 0];
            ulonglong2 b1 = *(const ulonglong2*)&Bs[kk][tx * 8 + 4];
            unsigned long long av[8] = {a0.x, a0.y, a1.x, a1.y, a2.x, a2.y, a3.x, a3.y};
            unsigned long long bv[4] = {b0.x, b0.y, b1.x, b1.y};
            #pragma unroll
            for (int i = 0; i < 8; i++)
                #pragma unroll
                for (int j = 0; j < 4; j++)
                    asm("fma.rn.f32x2 %0, %1, %2, %0;"
                        : "+l"(acc[i][j]) : "l"(av[i]), "l"(bv[j]));
        }
        __syncthreads();
    }

    if (!FUSE) {
        #pragma unroll
        for (int i = 0; i < 8; i++) {
            float2 f0 = *(float2*)&acc[i][0];
            float2 f1 = *(float2*)&acc[i][1];
            float2 f2 = *(float2*)&acc[i][2];
            float2 f3 = *(float2*)&acc[i][3];
            size_t off = (size_t)(brow + ty * 8 + i) * Nv + bcol + tx * 8;
            *(float4*)(C + off)     = make_float4(f0.x, f0.y, f1.x, f1.y);
            *(float4*)(C + off + 4) = make_float4(f2.x, f2.y, f3.x, f3.y);
        }
    } else {
        if (tid < 128) rowsum[tid] = 0.f;
        __syncthreads();
        #pragma unroll
        for (int i = 0; i < 8; i++) {
            int grow = brow + ty * 8 + i;
            float p = 0.f;
            #pragma unroll
            for (int j = 0; j < 4; j++) {
                float2 f = *(float2*)&acc[i][j];
                float e0 = fexp(InvT * f.x);
                float e1 = fexp(InvT * f.y);
                p += e0 + e1;
                int c = bcol + tx * 8 + j * 2;
                if (c == grow)     gdiag[grow] = e0;
                if (c + 1 == grow) gdiag[grow] = e1;
            }
            atomicAdd(&rowsum[ty * 8 + i], p);
        }
        __syncthreads();
        if (tid < 128) atomicAdd(&gs[brow + tid], rowsum[tid]);
    }
}

// ---------------- small SGEMM (NN, scalar) ----------------
template<int BM, int BN, int BK, int TM, int TN>
__global__ void sgemm_nn_k(const float* A, const float* B, float* C,
                           int M, int Nc, int Kk) {
    __shared__ float As[BK][BM];
    __shared__ float Bs[BK][BN];
    constexpr int THREADS = (BM / TM) * (BN / TN);
    int tid = threadIdx.x;
    int brow = blockIdx.y * BM, bcol = blockIdx.x * BN;
    int tx = tid % (BN / TN);
    int ty = tid / (BN / TN);
    float acc[TM][TN] = {};
    float ra[TM], rb[TN];
    for (int k0 = 0; k0 < Kk; k0 += BK) {
        constexpr int ALD = BM * BK / THREADS / 4;
        #pragma unroll
        for (int l = 0; l < ALD; l++) {
            int li = tid + l * THREADS;
            int m = li / (BK / 4);
            int kq = li % (BK / 4);
            float4 v = *(const float4*)(A + (size_t)(brow + m) * Kk + k0 + kq * 4);
            As[kq * 4 + 0][m] = v.x; As[kq * 4 + 1][m] = v.y;
            As[kq * 4 + 2][m] = v.z; As[kq * 4 + 3][m] = v.w;
        }
        constexpr int BLD = BN * BK / THREADS / 4;
        #pragma unroll
        for (int l = 0; l < BLD; l++) {
            int li = tid + l * THREADS;
            int kk = li / (BN / 4);
            int nq = li % (BN / 4);
            float4 v = *(const float4*)(B + (size_t)(k0 + kk) * Nc + bcol + nq * 4);
            *(float4*)&Bs[kk][nq * 4] = v;
        }
        __syncthreads();
        #pragma unroll
        for (int kk = 0; kk < BK; kk++) {
            #pragma unroll
            for (int i = 0; i < TM; i++) ra[i] = As[kk][ty * TM + i];
            #pragma unroll
            for (int j = 0; j < TN; j++) rb[j] = Bs[kk][tx * TN + j];
            #pragma unroll
            for (int i = 0; i < TM; i++)
                #pragma unroll
                for (int j = 0; j < TN; j++) acc[i][j] += ra[i] * rb[j];
        }
        __syncthreads();
    }
    #pragma unroll
    for (int i = 0; i < TM; i++)
        #pragma unroll
        for (int j = 0; j < TN; j += 4) {
            float4 v = make_float4(acc[i][j], acc[i][j+1], acc[i][j+2], acc[i][j+3]);
            *(float4*)(C + (size_t)(brow + ty * TM + i) * Nc + bcol + tx * TN + j) = v;
        }
}

// ---------------- top-k (iterative argmax, tie -> lowest index) ----------------
__global__ void topk_k(const float* sim, int* topi, float* topv) {
    __shared__ float sv[Nv];
    __shared__ float bv[256];
    __shared__ int   bi[256];
    int r = blockIdx.x, t = threadIdx.x;
    for (int i = t; i < Nv; i += 256) sv[i] = sim[(size_t)r * Nv + i];
    __syncthreads();
    for (int k = 0; k < Kp; k++) {
        float best = -1e30f; int besti = Nv;
        for (int i = t; i < Nv; i += 256) {
            float v = sv[i];
            if (v > best || (v == best && i < besti)) { best = v; besti = i; }
        }
        bv[t] = best; bi[t] = besti; __syncthreads();
        for (int s = 128; s > 0; s >>= 1) {
            if (t < s) {
                if (bv[t + s] > bv[t] || (bv[t + s] == bv[t] && bi[t + s] < bi[t])) {
                    bv[t] = bv[t + s]; bi[t] = bi[t + s];
                }
            }
            __syncthreads();
        }
        if (t == 0) {
            topv[r * Kp + k] = bv[0];
            topi[r * Kp + k] = bi[0];
            sv[bi[0]] = -1e30f;
        }
        __syncthreads();
    }
}

// scatter encoded values: W[r,c] = v + 2 (presence flag, since v >= -1)
__global__ void scatter_enc_k(const int* ti, const float* tv, float* W) {
    int i = blockIdx.x * blockDim.x + threadIdx.x;
    if (i >= Nv * Kp) return;
    int r = i / Kp;
    int c = ti[i];
    float v = tv[i];
    if (v != v) v = 0.f;   // nan_to_num
    W[(size_t)r * Nv + c] = v + 2.0f;
}

// symmetric combine, coalesced via 32x32 transpose tiles; emits COO of nonzeros
__global__ void wund_k(float* W, int* coo_i, int* coo_j, float* coo_w, int* nnz) {
    int bi = blockIdx.x, bj = blockIdx.y;
    if (bj < bi) return;
    __shared__ float T1[32][33];
    __shared__ float T2[32][33];
    __shared__ int lcnt, lbase;
    int tx = threadIdx.x, ty = threadIdx.y;
    int tid = ty * 32 + tx;
    if (tid == 0) lcnt = 0;
    T1[ty][tx] = W[(size_t)(bi * 32 + ty) * Nv + bj * 32 + tx];
    T2[ty][tx] = W[(size_t)(bj * 32 + ty) * Nv + bi * 32 + tx];
    __syncthreads();
    int i = bi * 32 + ty, j = bj * 32 + tx;
    float a = T1[ty][tx];          // encoded A[i][j]
    float b = T2[tx][ty];          // encoded A[j][i]
    float pa = (a > 0.f) ? 1.f : 0.f;
    float pb_ = (b > 0.f) ? 1.f : 0.f;
    float cnt = pa + pb_;
    float sum = (a - 2.f) * pa + (b - 2.f) * pb_;
    float o = (cnt > 0.f) ? fmaxf(sum / fmaxf(cnt, 1.f), 0.f) : 0.f;
    __syncthreads();               // done reading T1 before reuse
    W[(size_t)i * Nv + j] = o;
    T1[ty][tx] = o;
    int slot = -1;
    bool flag = (o > 0.f) && (j >= i);
    if (flag) slot = atomicAdd(&lcnt, 1);
    __syncthreads();
    W[(size_t)(bj * 32 + ty) * Nv + bi * 32 + tx] = T1[tx][ty];
    if (tid == 0 && lcnt > 0) lbase = atomicAdd(nnz, lcnt);
    __syncthreads();
    if (flag) {
        coo_i[lbase + slot] = i;
        coo_j[lbase + slot] = j;
        coo_w[lbase + slot] = o;
    }
}

// ---------------- dense-row-scan SpMM (Wund has ~34 nnz/row) ----------------
// EPI: 1 relu(v+bias), 2 elu(v+bias)+row normalize
template<int EPI>
__global__ void spmm_k(const float* __restrict__ W, const float* __restrict__ X,
                       const float* __restrict__ bias, float* __restrict__ out) {
    __shared__ int   si[256];
    __shared__ float sw[256];
    __shared__ int   scnt;
    __shared__ float red[256];
    int r = blockIdx.x, t = threadIdx.x;
    const float* wr = W + (size_t)r * Nv;
    float acc = 0.f;
    for (int base = 0; base < Nv; base += 256) {
        if (t == 0) scnt = 0;
        __syncthreads();
        float w = wr[base + t];
        if (w != 0.f) { int p = atomicAdd(&scnt, 1); si[p] = base + t; sw[p] = w; }
        __syncthreads();
        int c = scnt;
        for (int q = 0; q < c; q++) acc += sw[q] * X[(size_t)si[q] * Dh + t];
        __syncthreads();
    }
    float v = acc + bias[t];
    if (EPI == 1) {
        out[(size_t)r * Dh + t] = fmaxf(v, 0.f);
    } else {
        v = v > 0.f ? v : expm1f(v);
        red[t] = v * v; __syncthreads();
        for (int s = 128; s > 0; s >>= 1) { if (t < s) red[t] += red[t + s]; __syncthreads(); }
        out[(size_t)r * Dh + t] = v / (sqrtf(red[0]) + Eps);
    }
}

// ---------------- pf/pb over COO nonzeros (warp per entry) ----------------
__global__ void pfpb_k(const int* coo_i, const int* coo_j, const float* coo_w,
                       const int* nnz, const float* __restrict__ z1,
                       const float* __restrict__ z2, const float* gs,
                       float* pf, float* pb) {
    int wid = (blockIdx.x * blockDim.x + threadIdx.x) >> 5;
    int lane = threadIdx.x & 31;
    if (wid >= *nnz) return;
    int i = coo_i[wid], j = coo_j[wid];
    float wt = coo_w[wid];
    float d1 = 0.f, d2 = 0.f;
    #pragma unroll
    for (int q = 0; q < 8; q++) {
        int c = lane + q * 32;
        d1 += z1[(size_t)i * Dh + c] * z2[(size_t)j * Dh + c];
    }
    if (i != j) {
        #pragma unroll
        for (int q = 0; q < 8; q++) {
            int c = lane + q * 32;
            d2 += z1[(size_t)j * Dh + c] * z2[(size_t)i * Dh + c];
        }
    }
    #pragma unroll
    for (int o = 16; o > 0; o >>= 1) {
        d1 += __shfl_xor_sync(0xffffffffu, d1, o);
        d2 += __shfl_xor_sync(0xffffffffu, d2, o);
    }
    if (lane == 0) {
        float q1 = fexp(InvT * d1) / gs[i] * wt;
        atomicAdd(&pf[i], q1);
        atomicAdd(&pb[j], q1);
        if (i != j) {
            float q2 = fexp(InvT * d2) / gs[j] * wt;
            atomicAdd(&pf[j], q2);
            atomicAdd(&pb[i], q2);
        }
    }
}

__global__ void loss_k(const float* gdiag, const float* gs,
                       const float* pf, const float* pb, float* out) {
    __shared__ float s1[256], s2[256], s3[256];
    int t = threadIdx.x;
    float a = 0.f, b = 0.f, c = 0.f;
    for (int i = t; i < Nv; i += 256) {
        a -= logf(fmaxf(gdiag[i] / gs[i], Eps));
        b -= logf(fmaxf(pf[i], Eps));
        c -= logf(fmaxf(pb[i], Eps));
    }
    s1[t] = a; s2[t] = b; s3[t] = c; __syncthreads();
    for (int st = 128; st > 0; st >>= 1) {
        if (t < st) { s1[t] += s1[t + st]; s2[t] += s2[t + st]; s3[t] += s3[t + st]; }
        __syncthreads();
    }
    if (t == 0) out[0] = s1[0] / Nv + 0.5f * (s2[0] / Nv + s3[0] / Nv);
}

// ---------------- host launcher ----------------
extern "C" void kernel_launch(void* const* d_in, const int* in_sizes, int n_in,
                              void* d_out, int out_size) {
    const float* x       = (const float*)d_in[0];
    const int*   esrc    = (const int*)d_in[1];
    const int*   edst    = (const int*)d_in[2];
    const float* p_feat  = (const float*)d_in[3];
    const float* p_share = (const float*)d_in[4];
    const float* p_bal   = (const float*)d_in[5];
    const float* W1      = (const float*)d_in[6];
    const float* b1      = (const float*)d_in[7];
    const float* W2      = (const float*)d_in[8];
    const float* b2      = (const float*)d_in[9];
    float* out = (float*)d_out;
    int E = in_sizes[1];

    float* H = nullptr;
    cudaGetSymbolAddress((void**)&H, g_heap);
    float* sim  = H + O_SIM;  float* W    = H + O_W;
    float* x1   = H + O_X1;   float* agg  = H + O_AGG;  float* hn   = H + O_HN;
    float* xw1  = H + O_XW1;  float* bufA = H + O_BUFA; float* bufB = H + O_BUFB;
    float* z1   = H + O_Z1;   float* z2   = H + O_Z2;
    float* deg  = H + O_DEG;  float* dinv = H + O_DINV;
    float* gs   = H + O_GS;   float* pf   = H + O_PF;   float* pb   = H + O_PB;
    float* gd   = H + O_GD;
    int*   rptr = (int*)(H + O_RPTR);
    int*   fill = (int*)(H + O_FILL);
    int*   csrc = (int*)(H + O_CSRC);
    int*   topi = (int*)(H + O_TOPI);
    float* topv = H + O_TOPV;
    int*   cooi = (int*)(H + O_COOI);
    int*   cooj = (int*)(H + O_COOJ);
    float* coow = H + O_COOW;
    int*   nnz  = (int*)(H + O_NNZ);

    // GCN normalization + CSR build
    deg_init_k<<<(Nv + 255) / 256, 256>>>(deg);
    deg_count_k<<<(E + 255) / 256, 256>>>(edst, deg, E);
    dinv_k<<<(Nv + 255) / 256, 256>>>(deg, dinv);
    scan_k<<<1, 1024>>>(deg, rptr, fill);
    fill_k<<<(E + 255) / 256, 256>>>(esrc, edst, rptr, fill, csrc, E);

    // prompted features + first propagate + hn
    x1_k<<<(Nv * Din) / 256, 256>>>(x, p_feat, p_share, x1);
    prop_k<Din, 0><<<Nv, Din>>>(x1, rptr, csrc, dinv, nullptr, agg);
    hn_k<<<Nv, 256>>>(x1, agg, p_bal, hn);

    // sim = hn @ hn^T   (f32x2 GEMM)
    fgemm_nt_k<false><<<dim3(32, 32), 256>>>(hn, hn, sim, nullptr, nullptr, Dh);

    // top-(K+1) per row, reconstructed symmetric adjacency + COO
    topk_k<<<Nv, 256>>>(sim, topi, topv);
    zero_k<<<4096, 256>>>(W, NN);
    zero_i_k<<<1, 1>>>(nnz);
    scatter_enc_k<<<(Nv * Kp + 255) / 256, 256>>>(topi, topv, W);
    wund_k<<<dim3(128, 128), dim3(32, 32)>>>(W, cooi, cooj, coow, nnz);

    // xw1 = x1 @ W1
    sgemm_nn_k<64,64,16,4,4><<<dim3(Dh/64, Nv/64), 256>>>(x1, W1, xw1, Nv, Dh, Din);

    // view 1: sparse GCN (gather propagate, fused epilogues)
    prop_k<Dh, 1><<<Nv, Dh>>>(xw1, rptr, csrc, dinv, b1, bufA);           // h1
    sgemm_nn_k<64,64,16,4,4><<<dim3(Dh/64, Nv/64), 256>>>(bufA, W2, bufB, Nv, Dh, Dh);
    prop_k<Dh, 2><<<Nv, Dh>>>(bufB, rptr, csrc, dinv, b2, z1);            // z1 normalized

    // view 2: reconstructed graph (dense-row-scan SpMM, fused epilogues)
    spmm_k<1><<<Nv, 256>>>(W, xw1, b1, bufA);                              // g1
    sgemm_nn_k<64,64,16,4,4><<<dim3(Dh/64, Nv/64), 256>>>(bufA, W2, bufB, Nv, Dh, Dh);
    spmm_k<2><<<Nv, 256>>>(W, bufB, b2, z2);                               // z2 normalized

    // fused z1n @ z2n^T: row exp-sums + diag (no S materialization)
    zero_k<<<16, 256>>>(gs, (size_t)Nv * 3);                               // gs, pf, pb
    fgemm_nt_k<true><<<dim3(32, 32), 256>>>(z1, z2, nullptr, gs, gd, Dh);

    // pf/pb from COO nonzeros + final loss
    pfpb_k<<<COO_CAP / 8, 256>>>(cooi, cooj, coow, nnz, z1, z2, gs, pf, pb);
    loss_k<<<1, 256>>>(gd, gs, pf, pb, out);
}

// round 4
// speedup vs baseline: 1.9119x; 1.5274x over previous
#include <cuda_runtime.h>
#include <math.h>
#include <stdint.h>

// ---------------- problem constants ----------------
namespace {
constexpr int    Nv   = 4096;
constexpr int    Din  = 128;
constexpr int    Dh   = 256;
constexpr int    Kp   = 17;          // K+1
constexpr float  Eps  = 1e-8f;
constexpr float  InvT = 5.0f;        // 1/TEMP
constexpr size_t NN   = (size_t)Nv * (size_t)Nv;
constexpr int    Emax = 131072;
constexpr int    COO_CAP = 131072;

// scratch heap layout (units: floats)
constexpr size_t O_SIM  = 0;                            // N*N
constexpr size_t O_W    = O_SIM + NN;                   // N*N (encoded A -> Wund)
constexpr size_t O_X1   = O_W + NN;
constexpr size_t O_AGG  = O_X1  + (size_t)Nv*Din;
constexpr size_t O_HN   = O_AGG + (size_t)Nv*Din;
constexpr size_t O_XW1  = O_HN  + (size_t)Nv*Dh;
constexpr size_t O_BUFA = O_XW1 + (size_t)Nv*Dh;
constexpr size_t O_BUFB = O_BUFA+ (size_t)Nv*Dh;
constexpr size_t O_Z1   = O_BUFB+ (size_t)Nv*Dh;
constexpr size_t O_Z2   = O_Z1  + (size_t)Nv*Dh;
constexpr size_t O_DEG  = O_Z2  + (size_t)Nv*Dh;
constexpr size_t O_DINV = O_DEG + Nv;
constexpr size_t O_GS   = O_DINV+ Nv;                   // gs, pf, pb contiguous
constexpr size_t O_PF   = O_GS  + Nv;
constexpr size_t O_PB   = O_PF  + Nv;
constexpr size_t O_GD   = O_PB  + Nv;
constexpr size_t O_RPTR = O_GD  + Nv;                   // Nv+1 ints
constexpr size_t O_FILL = O_RPTR+ (Nv + 4);
constexpr size_t O_CSRC = O_FILL+ Nv;                   // Emax ints
constexpr size_t O_TOPI = O_CSRC+ Emax;                 // Nv*Kp ints
constexpr size_t O_TOPV = O_TOPI+ (size_t)Nv*Kp;
constexpr size_t O_COOI = O_TOPV+ (size_t)Nv*Kp;
constexpr size_t O_COOJ = O_COOI+ COO_CAP;
constexpr size_t O_COOW = O_COOJ+ COO_CAP;
constexpr size_t O_NNZ  = O_COOW+ COO_CAP;
constexpr size_t TOTAL  = O_NNZ + 4;
}

__device__ __align__(256) float g_heap[TOTAL];

// ---------------- fast exp (FMA only, |x| <= ~8) ----------------
__device__ __forceinline__ float fexp(float x) {
    float t  = x * 1.4426950408889634f;
    float rf = __fadd_rn(t, 12582912.0f);
    int   e  = __float_as_int(rf) - 0x4B400000;
    float r  = __fadd_rn(rf, -12582912.0f);
    float f  = t - r;
    float p  = fmaf(1.5403530394e-4f, f, 1.3333558146e-3f);
    p = fmaf(p, f, 9.6181291076e-3f);
    p = fmaf(p, f, 5.5504108665e-2f);
    p = fmaf(p, f, 2.4022650696e-1f);
    p = fmaf(p, f, 6.9314718056e-1f);
    p = fmaf(p, f, 1.0f);
    return __int_as_float(__float_as_int(p) + (e << 23));
}

// ---------------- mma.sync helpers (arch-generic, sm_80+) ----------------
// pack two floats to bf16x2: low half = e (even k), high half = o (odd k)
__device__ __forceinline__ uint32_t pack2(float e, float o) {
    uint32_t r;
    asm("cvt.rn.bf16x2.f32 %0, %1, %2;" : "=r"(r) : "f"(o), "f"(e));
    return r;
}
__device__ __forceinline__ void mma_bf16(float* c, const uint32_t* a, const uint32_t* b) {
    asm volatile(
        "mma.sync.aligned.m16n8k16.row.col.f32.bf16.bf16.f32 "
        "{%0,%1,%2,%3}, {%4,%5,%6,%7}, {%8,%9}, {%0,%1,%2,%3};"
        : "+f"(c[0]), "+f"(c[1]), "+f"(c[2]), "+f"(c[3])
        : "r"(a[0]), "r"(a[1]), "r"(a[2]), "r"(a[3]), "r"(b[0]), "r"(b[1]));
}

// ---------------- small utility kernels ----------------
__global__ void zero_k(float* p, size_t n) {
    size_t i = (size_t)blockIdx.x * blockDim.x + threadIdx.x;
    size_t stride = (size_t)gridDim.x * blockDim.x;
    for (; i < n; i += stride) p[i] = 0.f;
}
__global__ void zero_i_k(int* p) { p[0] = 0; }

__global__ void deg_init_k(float* deg) {
    int i = blockIdx.x * blockDim.x + threadIdx.x;
    if (i < Nv) deg[i] = 1.f;
}
__global__ void deg_count_k(const int* dst, float* deg, int E) {
    int e = blockIdx.x * blockDim.x + threadIdx.x;
    if (e < E) atomicAdd(&deg[dst[e]], 1.f);
}
__global__ void dinv_k(const float* deg, float* dinv) {
    int i = blockIdx.x * blockDim.x + threadIdx.x;
    if (i < Nv) dinv[i] = rsqrtf(deg[i]);
}

__global__ void x1_k(const float* x, const float* pf, const float* ps, float* x1) {
    int i = blockIdx.x * blockDim.x + threadIdx.x;
    if (i >= Nv * Din) return;
    int c = i % Din;
    float v = x[i] * pf[c];
    x1[i] = fmaxf(v, 0.f) * ps[c];
}

// ---------------- CSR build ----------------
__global__ void scan_k(const float* deg, int* rowptr, int* fill) {
    __shared__ int s[1024];
    int t = threadIdx.x;
    int c[4]; int loc = 0;
    #pragma unroll
    for (int q = 0; q < 4; q++) { c[q] = (int)deg[t * 4 + q] - 1; loc += c[q]; }
    s[t] = loc; __syncthreads();
    for (int off = 1; off < 1024; off <<= 1) {
        int v = (t >= off) ? s[t - off] : 0;
        __syncthreads();
        s[t] += v;
        __syncthreads();
    }
    int run = s[t] - loc;
    #pragma unroll
    for (int q = 0; q < 4; q++) {
        rowptr[t * 4 + q] = run; run += c[q];
        fill[t * 4 + q] = 0;
    }
    if (t == 1023) rowptr[Nv] = run;
}

__global__ void fill_k(const int* es, const int* ed, const int* rowptr,
                       int* fill, int* csrc, int E) {
    int e = blockIdx.x * blockDim.x + threadIdx.x;
    if (e >= E) return;
    int d = ed[e];
    int p = rowptr[d] + atomicAdd(&fill[d], 1);
    csrc[p] = es[e];
}

// ---------------- CSR gather propagate (atomic-free) ----------------
template<int F, int EPI>
__global__ void prop_k(const float* __restrict__ X, const int* __restrict__ rowptr,
                       const int* __restrict__ csrc, const float* __restrict__ dinv,
                       const float* __restrict__ bias, float* __restrict__ out) {
    __shared__ int   sI[F];
    __shared__ float sW[F];
    __shared__ float red[(EPI == 2) ? F : 1];
    int r = blockIdx.x, t = threadIdx.x;
    int beg = rowptr[r], end = rowptr[r + 1];
    float acc = 0.f;
    for (int base = beg; base < end; base += F) {
        int m = min(F, end - base);
        if (t < m) { int s = csrc[base + t]; sI[t] = s; sW[t] = dinv[s]; }
        __syncthreads();
        #pragma unroll 4
        for (int q = 0; q < m; q++) acc += sW[q] * X[(size_t)sI[q] * F + t];
        __syncthreads();
    }
    float dv = dinv[r];
    float v = dv * dv * X[(size_t)r * F + t] + dv * acc;
    if (EPI == 0) {
        out[(size_t)r * F + t] = v;
    } else if (EPI == 1) {
        out[(size_t)r * F + t] = fmaxf(v + bias[t], 0.f);
    } else {
        v += bias[t];
        v = v > 0.f ? v : expm1f(v);
        red[t] = v * v; __syncthreads();
        for (int s = F / 2; s > 0; s >>= 1) { if (t < s) red[t] += red[t + s]; __syncthreads(); }
        out[(size_t)r * F + t] = v / (sqrtf(red[0]) + Eps);
    }
}

__global__ void hn_k(const float* x1, const float* agg, const float* pbal, float* hn) {
    __shared__ float sh[256];
    int r = blockIdx.x, t = threadIdx.x;
    float v = (t < Din ? x1[(size_t)r * Din + t] : agg[(size_t)r * Din + (t - Din)]) * pbal[t];
    sh[t] = v * v; __syncthreads();
    for (int s = 128; s > 0; s >>= 1) { if (t < s) sh[t] += sh[t + s]; __syncthreads(); }
    float nrm = sqrtf(sh[0]);
    hn[(size_t)r * Dh + t] = v / (nrm + Eps);
}

// ---------------- big NT GEMM via mma.sync bf16 (3-term split) ----------------
// C[4096,4096] = A[4096,256] * B[4096,256]^T.
// sym: only compute upper tiles (bx>=by), mirror-write lower half.
// FUSE: no C write; gs[r] += sum_j fexp(5*c_rj), gdiag[r] = fexp(5*c_rr).
template<bool FUSE>
__global__ __launch_bounds__(256)
void mma_nt_k(const float* __restrict__ A, const float* __restrict__ B,
              float* __restrict__ C, float* __restrict__ gs,
              float* __restrict__ gdiag, int sym) {
    __shared__ uint32_t AHI[128][20];   // [row][k2], 16 used + 4 pad (bank-safe)
    __shared__ uint32_t ALO[128][20];
    __shared__ uint32_t BHI[128][20];
    __shared__ uint32_t BLO[128][20];
    __shared__ float rowsum[128];

    int bx = blockIdx.x, by = blockIdx.y;
    if (sym && by > bx) return;
    int brow = by * 128, bcol = bx * 128;
    int tid = threadIdx.x;
    int lane = tid & 31, wid = tid >> 5;
    int g = lane >> 2, tg = lane & 3;
    int wm = (wid >> 1) * 32, wn = (wid & 1) * 64;

    float acc[2][8][4];
    #pragma unroll
    for (int mt = 0; mt < 2; mt++)
        #pragma unroll
        for (int nt = 0; nt < 8; nt++)
            #pragma unroll
            for (int q = 0; q < 4; q++) acc[mt][nt][q] = 0.f;

    for (int c = 0; c < 8; c++) {
        int k0 = c * 32;
        __syncthreads();
        #pragma unroll
        for (int l = 0; l < 4; l++) {
            int idx = tid + l * 256;
            int row = idx >> 3, q = idx & 7;
            // A
            float4 v = *(const float4*)(A + (size_t)(brow + row) * 256 + k0 + q * 4);
            uint32_t h0 = pack2(v.x, v.y);
            uint32_t h1 = pack2(v.z, v.w);
            float ex = __uint_as_float(h0 << 16);
            float ox = __uint_as_float(h0 & 0xffff0000u);
            float ez = __uint_as_float(h1 << 16);
            float ow = __uint_as_float(h1 & 0xffff0000u);
            uint32_t l0 = pack2(v.x - ex, v.y - ox);
            uint32_t l1 = pack2(v.z - ez, v.w - ow);
            *(uint2*)&AHI[row][q * 2] = make_uint2(h0, h1);
            *(uint2*)&ALO[row][q * 2] = make_uint2(l0, l1);
            // B
            v = *(const float4*)(B + (size_t)(bcol + row) * 256 + k0 + q * 4);
            h0 = pack2(v.x, v.y);
            h1 = pack2(v.z, v.w);
            ex = __uint_as_float(h0 << 16);
            ox = __uint_as_float(h0 & 0xffff0000u);
            ez = __uint_as_float(h1 << 16);
            ow = __uint_as_float(h1 & 0xffff0000u);
            l0 = pack2(v.x - ex, v.y - ox);
            l1 = pack2(v.z - ez, v.w - ow);
            *(uint2*)&BHI[row][q * 2] = make_uint2(h0, h1);
            *(uint2*)&BLO[row][q * 2] = make_uint2(l0, l1);
        }
        __syncthreads();
        #pragma unroll
        for (int s2 = 0; s2 < 2; s2++) {
            int kb = s2 * 8;
            uint32_t ahi[2][4], alo[2][4];
            #pragma unroll
            for (int mt = 0; mt < 2; mt++) {
                int rb = wm + mt * 16;
                ahi[mt][0] = AHI[rb + g][kb + tg];
                ahi[mt][1] = AHI[rb + g + 8][kb + tg];
                ahi[mt][2] = AHI[rb + g][kb + tg + 4];
                ahi[mt][3] = AHI[rb + g + 8][kb + tg + 4];
                alo[mt][0] = ALO[rb + g][kb + tg];
                alo[mt][1] = ALO[rb + g + 8][kb + tg];
                alo[mt][2] = ALO[rb + g][kb + tg + 4];
                alo[mt][3] = ALO[rb + g + 8][kb + tg + 4];
            }
            #pragma unroll
            for (int nh = 0; nh < 2; nh++) {
                uint32_t bhi[4][2], blo[4][2];
                #pragma unroll
                for (int n4 = 0; n4 < 4; n4++) {
                    int cb = wn + (nh * 4 + n4) * 8;
                    bhi[n4][0] = BHI[cb + g][kb + tg];
                    bhi[n4][1] = BHI[cb + g][kb + tg + 4];
                    blo[n4][0] = BLO[cb + g][kb + tg];
                    blo[n4][1] = BLO[cb + g][kb + tg + 4];
                }
                #pragma unroll
                for (int mt = 0; mt < 2; mt++)
                    #pragma unroll
                    for (int n4 = 0; n4 < 4; n4++) {
                        float* cc = acc[mt][nh * 4 + n4];
                        mma_bf16(cc, ahi[mt], bhi[n4]);
                        mma_bf16(cc, ahi[mt], blo[n4]);
                        mma_bf16(cc, alo[mt], bhi[n4]);
                    }
            }
        }
    }

    if (!FUSE) {
        #pragma unroll
        for (int mt = 0; mt < 2; mt++)
            #pragma unroll
            for (int nt = 0; nt < 8; nt++) {
                int r0 = brow + wm + mt * 16 + g;
                int c0 = bcol + wn + nt * 8 + 2 * tg;
                float2 v01 = make_float2(acc[mt][nt][0], acc[mt][nt][1]);
                float2 v23 = make_float2(acc[mt][nt][2], acc[mt][nt][3]);
                *(float2*)(C + (size_t)r0 * Nv + c0)       = v01;
                *(float2*)(C + (size_t)(r0 + 8) * Nv + c0) = v23;
                if (sym && bx != by) {
                    C[(size_t)c0 * Nv + r0]           = v01.x;
                    C[(size_t)(c0 + 1) * Nv + r0]     = v01.y;
                    C[(size_t)c0 * Nv + r0 + 8]       = v23.x;
                    C[(size_t)(c0 + 1) * Nv + r0 + 8] = v23.y;
                }
            }
    } else {
        if (tid < 128) rowsum[tid] = 0.f;
        __syncthreads();
        #pragma unroll
        for (int mt = 0; mt < 2; mt++) {
            int lr0 = wm + mt * 16 + g;
            int gr0 = brow + lr0;
            float rs0 = 0.f, rs1 = 0.f;
            #pragma unroll
            for (int nt = 0; nt < 8; nt++) {
                int gc = bcol + wn + nt * 8 + 2 * tg;
                float e0 = fexp(InvT * acc[mt][nt][0]);
                float e1 = fexp(InvT * acc[mt][nt][1]);
                float e2 = fexp(InvT * acc[mt][nt][2]);
                float e3 = fexp(InvT * acc[mt][nt][3]);
                rs0 += e0 + e1;
                rs1 += e2 + e3;
                if (gc == gr0)         gdiag[gr0] = e0;
                if (gc + 1 == gr0)     gdiag[gr0] = e1;
                if (gc == gr0 + 8)     gdiag[gr0 + 8] = e2;
                if (gc + 1 == gr0 + 8) gdiag[gr0 + 8] = e3;
            }
            rs0 += __shfl_xor_sync(0xffffffffu, rs0, 1);
            rs0 += __shfl_xor_sync(0xffffffffu, rs0, 2);
            rs1 += __shfl_xor_sync(0xffffffffu, rs1, 1);
            rs1 += __shfl_xor_sync(0xffffffffu, rs1, 2);
            if (tg == 0) {
                atomicAdd(&rowsum[lr0], rs0);
                atomicAdd(&rowsum[lr0 + 8], rs1);
            }
        }
        __syncthreads();
        if (tid < 128) atomicAdd(&gs[brow + tid], rowsum[tid]);
    }
}

// ---------------- small SGEMM (NN, scalar) ----------------
template<int BM, int BN, int BK, int TM, int TN>
__global__ void sgemm_nn_k(const float* A, const float* B, float* C,
                           int M, int Nc, int Kk) {
    __shared__ float As[BK][BM];
    __shared__ float Bs[BK][BN];
    constexpr int THREADS = (BM / TM) * (BN / TN);
    int tid = threadIdx.x;
    int brow = blockIdx.y * BM, bcol = blockIdx.x * BN;
    int tx = tid % (BN / TN);
    int ty = tid / (BN / TN);
    float acc[TM][TN] = {};
    float ra[TM], rb[TN];
    for (int k0 = 0; k0 < Kk; k0 += BK) {
        constexpr int ALD = BM * BK / THREADS / 4;
        #pragma unroll
        for (int l = 0; l < ALD; l++) {
            int li = tid + l * THREADS;
            int m = li / (BK / 4);
            int kq = li % (BK / 4);
            float4 v = *(const float4*)(A + (size_t)(brow + m) * Kk + k0 + kq * 4);
            As[kq * 4 + 0][m] = v.x; As[kq * 4 + 1][m] = v.y;
            As[kq * 4 + 2][m] = v.z; As[kq * 4 + 3][m] = v.w;
        }
        constexpr int BLD = BN * BK / THREADS / 4;
        #pragma unroll
        for (int l = 0; l < BLD; l++) {
            int li = tid + l * THREADS;
            int kk = li / (BN / 4);
            int nq = li % (BN / 4);
            float4 v = *(const float4*)(B + (size_t)(k0 + kk) * Nc + bcol + nq * 4);
            *(float4*)&Bs[kk][nq * 4] = v;
        }
        __syncthreads();
        #pragma unroll
        for (int kk = 0; kk < BK; kk++) {
            #pragma unroll
            for (int i = 0; i < TM; i++) ra[i] = As[kk][ty * TM + i];
            #pragma unroll
            for (int j = 0; j < TN; j++) rb[j] = Bs[kk][tx * TN + j];
            #pragma unroll
            for (int i = 0; i < TM; i++)
                #pragma unroll
                for (int j = 0; j < TN; j++) acc[i][j] += ra[i] * rb[j];
        }
        __syncthreads();
    }
    #pragma unroll
    for (int i = 0; i < TM; i++)
        #pragma unroll
        for (int j = 0; j < TN; j += 4) {
            float4 v = make_float4(acc[i][j], acc[i][j+1], acc[i][j+2], acc[i][j+3]);
            *(float4*)(C + (size_t)(brow + ty * TM + i) * Nc + bcol + tx * TN + j) = v;
        }
}

// ---------------- top-k (iterative argmax, warp-shuffle reduce) ----------------
__global__ void topk_k(const float* sim, int* topi, float* topv) {
    __shared__ float sv[Nv];
    __shared__ float sbv[8];
    __shared__ int   sbi[8];
    int r = blockIdx.x, t = threadIdx.x;
    for (int i = t; i < Nv; i += 256) sv[i] = sim[(size_t)r * Nv + i];
    __syncthreads();
    for (int k = 0; k < Kp; k++) {
        float best = -1e30f; int besti = Nv;
        for (int i = t; i < Nv; i += 256) {
            float v = sv[i];
            if (v > best || (v == best && i < besti)) { best = v; besti = i; }
        }
        #pragma unroll
        for (int o = 16; o > 0; o >>= 1) {
            float ov = __shfl_down_sync(0xffffffffu, best, o);
            int   oi = __shfl_down_sync(0xffffffffu, besti, o);
            if (ov > best || (ov == best && oi < besti)) { best = ov; besti = oi; }
        }
        if ((t & 31) == 0) { sbv[t >> 5] = best; sbi[t >> 5] = besti; }
        __syncthreads();
        if (t == 0) {
            float bb = sbv[0]; int bj = sbi[0];
            #pragma unroll
            for (int w = 1; w < 8; w++)
                if (sbv[w] > bb || (sbv[w] == bb && sbi[w] < bj)) { bb = sbv[w]; bj = sbi[w]; }
            topv[r * Kp + k] = bb;
            topi[r * Kp + k] = bj;
            sv[bj] = -1e30f;
        }
        __syncthreads();
    }
}

__global__ void scatter_enc_k(const int* ti, const float* tv, float* W) {
    int i = blockIdx.x * blockDim.x + threadIdx.x;
    if (i >= Nv * Kp) return;
    int r = i / Kp;
    int c = ti[i];
    float v = tv[i];
    if (v != v) v = 0.f;
    W[(size_t)r * Nv + c] = v + 2.0f;
}

__global__ void wund_k(float* W, int* coo_i, int* coo_j, float* coo_w, int* nnz) {
    int bi = blockIdx.x, bj = blockIdx.y;
    if (bj < bi) return;
    __shared__ float T1[32][33];
    __shared__ float T2[32][33];
    __shared__ int lcnt, lbase;
    int tx = threadIdx.x, ty = threadIdx.y;
    int tid = ty * 32 + tx;
    if (tid == 0) lcnt = 0;
    T1[ty][tx] = W[(size_t)(bi * 32 + ty) * Nv + bj * 32 + tx];
    T2[ty][tx] = W[(size_t)(bj * 32 + ty) * Nv + bi * 32 + tx];
    __syncthreads();
    int i = bi * 32 + ty, j = bj * 32 + tx;
    float a = T1[ty][tx];
    float b = T2[tx][ty];
    float pa = (a > 0.f) ? 1.f : 0.f;
    float pb_ = (b > 0.f) ? 1.f : 0.f;
    float cnt = pa + pb_;
    float sum = (a - 2.f) * pa + (b - 2.f) * pb_;
    float o = (cnt > 0.f) ? fmaxf(sum / fmaxf(cnt, 1.f), 0.f) : 0.f;
    __syncthreads();
    W[(size_t)i * Nv + j] = o;
    T1[ty][tx] = o;
    int slot = -1;
    bool flag = (o > 0.f) && (j >= i);
    if (flag) slot = atomicAdd(&lcnt, 1);
    __syncthreads();
    W[(size_t)(bj * 32 + ty) * Nv + bi * 32 + tx] = T1[tx][ty];
    if (tid == 0 && lcnt > 0) lbase = atomicAdd(nnz, lcnt);
    __syncthreads();
    if (flag) {
        coo_i[lbase + slot] = i;
        coo_j[lbase + slot] = j;
        coo_w[lbase + slot] = o;
    }
}

// ---------------- dense-row-scan SpMM ----------------
template<int EPI>
__global__ void spmm_k(const float* __restrict__ W, const float* __restrict__ X,
                       const float* __restrict__ bias, float* __restrict__ out) {
    __shared__ int   si[256];
    __shared__ float sw[256];
    __shared__ int   scnt;
    __shared__ float red[256];
    int r = blockIdx.x, t = threadIdx.x;
    const float* wr = W + (size_t)r * Nv;
    float acc = 0.f;
    for (int base = 0; base < Nv; base += 256) {
        if (t == 0) scnt = 0;
        __syncthreads();
        float w = wr[base + t];
        if (w != 0.f) { int p = atomicAdd(&scnt, 1); si[p] = base + t; sw[p] = w; }
        __syncthreads();
        int c = scnt;
        for (int q = 0; q < c; q++) acc += sw[q] * X[(size_t)si[q] * Dh + t];
        __syncthreads();
    }
    float v = acc + bias[t];
    if (EPI == 1) {
        out[(size_t)r * Dh + t] = fmaxf(v, 0.f);
    } else {
        v = v > 0.f ? v : expm1f(v);
        red[t] = v * v; __syncthreads();
        for (int s = 128; s > 0; s >>= 1) { if (t < s) red[t] += red[t + s]; __syncthreads(); }
        out[(size_t)r * Dh + t] = v / (sqrtf(red[0]) + Eps);
    }
}

// ---------------- pf/pb over COO nonzeros (warp per entry) ----------------
__global__ void pfpb_k(const int* coo_i, const int* coo_j, const float* coo_w,
                       const int* nnz, const float* __restrict__ z1,
                       const float* __restrict__ z2, const float* gs,
                       float* pf, float* pb) {
    int wid = (blockIdx.x * blockDim.x + threadIdx.x) >> 5;
    int lane = threadIdx.x & 31;
    if (wid >= *nnz) return;
    int i = coo_i[wid], j = coo_j[wid];
    float wt = coo_w[wid];
    float d1 = 0.f, d2 = 0.f;
    #pragma unroll
    for (int q = 0; q < 8; q++) {
        int c = lane + q * 32;
        d1 += z1[(size_t)i * Dh + c] * z2[(size_t)j * Dh + c];
    }
    if (i != j) {
        #pragma unroll
        for (int q = 0; q < 8; q++) {
            int c = lane + q * 32;
            d2 += z1[(size_t)j * Dh + c] * z2[(size_t)i * Dh + c];
        }
    }
    #pragma unroll
    for (int o = 16; o > 0; o >>= 1) {
        d1 += __shfl_xor_sync(0xffffffffu, d1, o);
        d2 += __shfl_xor_sync(0xffffffffu, d2, o);
    }
    if (lane == 0) {
        float q1 = fexp(InvT * d1) / gs[i] * wt;
        atomicAdd(&pf[i], q1);
        atomicAdd(&pb[j], q1);
        if (i != j) {
            float q2 = fexp(InvT * d2) / gs[j] * wt;
            atomicAdd(&pf[j], q2);
            atomicAdd(&pb[i], q2);
        }
    }
}

__global__ void loss_k(const float* gdiag, const float* gs,
                       const float* pf, const float* pb, float* out) {
    __shared__ float s1[256], s2[256], s3[256];
    int t = threadIdx.x;
    float a = 0.f, b = 0.f, c = 0.f;
    for (int i = t; i < Nv; i += 256) {
        a -= logf(fmaxf(gdiag[i] / gs[i], Eps));
        b -= logf(fmaxf(pf[i], Eps));
        c -= logf(fmaxf(pb[i], Eps));
    }
    s1[t] = a; s2[t] = b; s3[t] = c; __syncthreads();
    for (int st = 128; st > 0; st >>= 1) {
        if (t < st) { s1[t] += s1[t + st]; s2[t] += s2[t + st]; s3[t] += s3[t + st]; }
        __syncthreads();
    }
    if (t == 0) out[0] = s1[0] / Nv + 0.5f * (s2[0] / Nv + s3[0] / Nv);
}

// ---------------- host launcher ----------------
extern "C" void kernel_launch(void* const* d_in, const int* in_sizes, int n_in,
                              void* d_out, int out_size) {
    const float* x       = (const float*)d_in[0];
    const int*   esrc    = (const int*)d_in[1];
    const int*   edst    = (const int*)d_in[2];
    const float* p_feat  = (const float*)d_in[3];
    const float* p_share = (const float*)d_in[4];
    const float* p_bal   = (const float*)d_in[5];
    const float* W1      = (const float*)d_in[6];
    const float* b1      = (const float*)d_in[7];
    const float* W2      = (const float*)d_in[8];
    const float* b2      = (const float*)d_in[9];
    float* out = (float*)d_out;
    int E = in_sizes[1];

    float* H = nullptr;
    cudaGetSymbolAddress((void**)&H, g_heap);
    float* sim  = H + O_SIM;  float* W    = H + O_W;
    float* x1   = H + O_X1;   float* agg  = H + O_AGG;  float* hn   = H + O_HN;
    float* xw1  = H + O_XW1;  float* bufA = H + O_BUFA; float* bufB = H + O_BUFB;
    float* z1   = H + O_Z1;   float* z2   = H + O_Z2;
    float* deg  = H + O_DEG;  float* dinv = H + O_DINV;
    float* gs   = H + O_GS;   float* pf   = H + O_PF;   float* pb   = H + O_PB;
    float* gd   = H + O_GD;
    int*   rptr = (int*)(H + O_RPTR);
    int*   fill = (int*)(H + O_FILL);
    int*   csrc = (int*)(H + O_CSRC);
    int*   topi = (int*)(H + O_TOPI);
    float* topv = H + O_TOPV;
    int*   cooi = (int*)(H + O_COOI);
    int*   cooj = (int*)(H + O_COOJ);
    float* coow = H + O_COOW;
    int*   nnz  = (int*)(H + O_NNZ);

    // GCN normalization + CSR build
    deg_init_k<<<(Nv + 255) / 256, 256>>>(deg);
    deg_count_k<<<(E + 255) / 256, 256>>>(edst, deg, E);
    dinv_k<<<(Nv + 255) / 256, 256>>>(deg, dinv);
    scan_k<<<1, 1024>>>(deg, rptr, fill);
    fill_k<<<(E + 255) / 256, 256>>>(esrc, edst, rptr, fill, csrc, E);

    // prompted features + first propagate + hn
    x1_k<<<(Nv * Din) / 256, 256>>>(x, p_feat, p_share, x1);
    prop_k<Din, 0><<<Nv, Din>>>(x1, rptr, csrc, dinv, nullptr, agg);
    hn_k<<<Nv, 256>>>(x1, agg, p_bal, hn);

    // sim = hn @ hn^T via mma.sync bf16 split, symmetric (upper tiles + mirror)
    mma_nt_k<false><<<dim3(32, 32), 256>>>(hn, hn, sim, nullptr, nullptr, 1);

    // top-(K+1) per row, reconstructed symmetric adjacency + COO
    topk_k<<<Nv, 256>>>(sim, topi, topv);
    zero_k<<<4096, 256>>>(W, NN);
    zero_i_k<<<1, 1>>>(nnz);
    scatter_enc_k<<<(Nv * Kp + 255) / 256, 256>>>(topi, topv, W);
    wund_k<<<dim3(128, 128), dim3(32, 32)>>>(W, cooi, cooj, coow, nnz);

    // xw1 = x1 @ W1
    sgemm_nn_k<64,64,16,4,4><<<dim3(Dh/64, Nv/64), 256>>>(x1, W1, xw1, Nv, Dh, Din);

    // view 1: sparse GCN
    prop_k<Dh, 1><<<Nv, Dh>>>(xw1, rptr, csrc, dinv, b1, bufA);
    sgemm_nn_k<64,64,16,4,4><<<dim3(Dh/64, Nv/64), 256>>>(bufA, W2, bufB, Nv, Dh, Dh);
    prop_k<Dh, 2><<<Nv, Dh>>>(bufB, rptr, csrc, dinv, b2, z1);

    // view 2: reconstructed graph
    spmm_k<1><<<Nv, 256>>>(W, xw1, b1, bufA);
    sgemm_nn_k<64,64,16,4,4><<<dim3(Dh/64, Nv/64), 256>>>(bufA, W2, bufB, Nv, Dh, Dh);
    spmm_k<2><<<Nv, 256>>>(W, bufB, b2, z2);

    // fused z1n @ z2n^T via mma.sync: row exp-sums + diag
    zero_k<<<16, 256>>>(gs, (size_t)Nv * 3);
    mma_nt_k<true><<<dim3(32, 32), 256>>>(z1, z2, nullptr, gs, gd, 0);

    // pf/pb from COO nonzeros + final loss
    pfpb_k<<<COO_CAP / 8, 256>>>(cooi, cooj, coow, nnz, z1, z2, gs, pf, pb);
    loss_k<<<1, 256>>>(gd, gs, pf, pb, out);
}

// round 5
// speedup vs baseline: 3.0045x; 1.5715x over previous
#include <cuda_runtime.h>
#include <math.h>
#include <stdint.h>

// ---------------- problem constants ----------------
namespace {
constexpr int    Nv   = 4096;
constexpr int    Din  = 128;
constexpr int    Dh   = 256;
constexpr int    Kp   = 17;          // K+1
constexpr float  Eps  = 1e-8f;
constexpr float  InvT = 5.0f;        // 1/TEMP
constexpr size_t NN   = (size_t)Nv * (size_t)Nv;
constexpr int    Emax = 131072;
constexpr int    COO_CAP = 131072;
constexpr int    HCAP = 1 << 18;     // hash capacity (~70K keys -> load 0.27)
constexpr int    CSR2_CAP = 160000;

// scratch heap layout (units: floats)
constexpr size_t O_SIM  = 0;                            // N*N
constexpr size_t O_X1   = O_SIM + NN;
constexpr size_t O_AGG  = O_X1  + (size_t)Nv*Din;
constexpr size_t O_HN   = O_AGG + (size_t)Nv*Din;
constexpr size_t O_XW1  = O_HN  + (size_t)Nv*Dh;
constexpr size_t O_BUFA = O_XW1 + (size_t)Nv*Dh;
constexpr size_t O_BUFB = O_BUFA+ (size_t)Nv*Dh;
constexpr size_t O_Z1   = O_BUFB+ (size_t)Nv*Dh;
constexpr size_t O_Z2   = O_Z1  + (size_t)Nv*Dh;
constexpr size_t O_W1T  = O_Z2  + (size_t)Nv*Dh;        // 256x128
constexpr size_t O_W2T  = O_W1T + (size_t)Dh*Din;       // 256x256
constexpr size_t O_DEG  = O_W2T + (size_t)Dh*Dh;
constexpr size_t O_DINV = O_DEG + Nv;
constexpr size_t O_GS   = O_DINV+ Nv;                   // gs, pf, pb contiguous
constexpr size_t O_PF   = O_GS  + Nv;
constexpr size_t O_PB   = O_PF  + Nv;
constexpr size_t O_GD   = O_PB  + Nv;
constexpr size_t O_RPTR = O_GD  + Nv;                   // Nv+1 ints
constexpr size_t O_FILL = O_RPTR+ (Nv + 4);
constexpr size_t O_CSRC = O_FILL+ Nv;                   // Emax ints
constexpr size_t O_TOPI = O_CSRC+ Emax;                 // Nv*Kp ints
constexpr size_t O_TOPV = O_TOPI+ (size_t)Nv*Kp;
constexpr size_t O_COOI = O_TOPV+ (size_t)Nv*Kp;
constexpr size_t O_COOJ = O_COOI+ COO_CAP;
constexpr size_t O_COOW = O_COOJ+ COO_CAP;
constexpr size_t O_NNZ  = O_COOW+ COO_CAP;
constexpr size_t O_HKEY = O_NNZ + 4;                    // HCAP ints
constexpr size_t O_HSUM = O_HKEY+ HCAP;                 // HCAP floats
constexpr size_t O_HCNT = O_HSUM+ HCAP;                 // HCAP ints
constexpr size_t O_DEG2 = O_HCNT+ HCAP;                 // Nv ints
constexpr size_t O_RPT2 = O_DEG2+ Nv;                   // Nv+4 ints
constexpr size_t O_FIL2 = O_RPT2+ (Nv + 4);
constexpr size_t O_COL2 = O_FIL2+ Nv;                   // CSR2_CAP ints
constexpr size_t O_WCS2 = O_COL2+ CSR2_CAP;             // CSR2_CAP floats
constexpr size_t TOTAL  = O_WCS2+ CSR2_CAP;
}

__device__ __align__(256) float g_heap[TOTAL];

// ---------------- fast exp (FMA only, |x| <= ~8) ----------------
__device__ __forceinline__ float fexp(float x) {
    float t  = x * 1.4426950408889634f;
    float rf = __fadd_rn(t, 12582912.0f);
    int   e  = __float_as_int(rf) - 0x4B400000;
    float r  = __fadd_rn(rf, -12582912.0f);
    float f  = t - r;
    float p  = fmaf(1.5403530394e-4f, f, 1.3333558146e-3f);
    p = fmaf(p, f, 9.6181291076e-3f);
    p = fmaf(p, f, 5.5504108665e-2f);
    p = fmaf(p, f, 2.4022650696e-1f);
    p = fmaf(p, f, 6.9314718056e-1f);
    p = fmaf(p, f, 1.0f);
    return __int_as_float(__float_as_int(p) + (e << 23));
}

// ---------------- mma.sync helpers (arch-generic, sm_80+) ----------------
__device__ __forceinline__ uint32_t pack2(float e, float o) {
    uint32_t r;
    asm("cvt.rn.bf16x2.f32 %0, %1, %2;" : "=r"(r) : "f"(o), "f"(e));
    return r;
}
__device__ __forceinline__ void mma_bf16(float* c, const uint32_t* a, const uint32_t* b) {
    asm volatile(
        "mma.sync.aligned.m16n8k16.row.col.f32.bf16.bf16.f32 "
        "{%0,%1,%2,%3}, {%4,%5,%6,%7}, {%8,%9}, {%0,%1,%2,%3};"
        : "+f"(c[0]), "+f"(c[1]), "+f"(c[2]), "+f"(c[3])
        : "r"(a[0]), "r"(a[1]), "r"(a[2]), "r"(a[3]), "r"(b[0]), "r"(b[1]));
}

// ---------------- small utility kernels ----------------
__global__ void zero_k(float* p, size_t n) {
    size_t i = (size_t)blockIdx.x * blockDim.x + threadIdx.x;
    size_t stride = (size_t)gridDim.x * blockDim.x;
    for (; i < n; i += stride) p[i] = 0.f;
}

__global__ void deg_init_k(float* deg) {
    int i = blockIdx.x * blockDim.x + threadIdx.x;
    if (i < Nv) deg[i] = 1.f;
}
__global__ void deg_count_k(const int* dst, float* deg, int E) {
    int e = blockIdx.x * blockDim.x + threadIdx.x;
    if (e < E) atomicAdd(&deg[dst[e]], 1.f);
}
__global__ void dinv_k(const float* deg, float* dinv) {
    int i = blockIdx.x * blockDim.x + threadIdx.x;
    if (i < Nv) dinv[i] = rsqrtf(deg[i]);
}

__global__ void x1_k(const float* x, const float* pf, const float* ps, float* x1) {
    int i = blockIdx.x * blockDim.x + threadIdx.x;
    if (i >= Nv * Din) return;
    int c = i % Din;
    float v = x[i] * pf[c];
    x1[i] = fmaxf(v, 0.f) * ps[c];
}

__global__ void transpose_k(const float* __restrict__ A, float* __restrict__ AT,
                            int R, int Cc) {
    __shared__ float tile[32][33];
    int x = blockIdx.x * 32 + threadIdx.x;
    int y = blockIdx.y * 32 + threadIdx.y;
    tile[threadIdx.y][threadIdx.x] = A[(size_t)y * Cc + x];
    __syncthreads();
    int xo = blockIdx.y * 32 + threadIdx.x;
    int yo = blockIdx.x * 32 + threadIdx.y;
    AT[(size_t)yo * R + xo] = tile[threadIdx.x][threadIdx.y];
}

// ---------------- CSR build (original graph) ----------------
__global__ void scan_k(const float* deg, int* rowptr, int* fill) {
    __shared__ int s[1024];
    int t = threadIdx.x;
    int c[4]; int loc = 0;
    #pragma unroll
    for (int q = 0; q < 4; q++) { c[q] = (int)deg[t * 4 + q] - 1; loc += c[q]; }
    s[t] = loc; __syncthreads();
    for (int off = 1; off < 1024; off <<= 1) {
        int v = (t >= off) ? s[t - off] : 0;
        __syncthreads();
        s[t] += v;
        __syncthreads();
    }
    int run = s[t] - loc;
    #pragma unroll
    for (int q = 0; q < 4; q++) {
        rowptr[t * 4 + q] = run; run += c[q];
        fill[t * 4 + q] = 0;
    }
    if (t == 1023) rowptr[Nv] = run;
}

__global__ void fill_k(const int* es, const int* ed, const int* rowptr,
                       int* fill, int* csrc, int E) {
    int e = blockIdx.x * blockDim.x + threadIdx.x;
    if (e >= E) return;
    int d = ed[e];
    int p = rowptr[d] + atomicAdd(&fill[d], 1);
    csrc[p] = es[e];
}

// ---------------- CSR gather propagate (atomic-free) ----------------
template<int F, int EPI>
__global__ void prop_k(const float* __restrict__ X, const int* __restrict__ rowptr,
                       const int* __restrict__ csrc, const float* __restrict__ dinv,
                       const float* __restrict__ bias, float* __restrict__ out) {
    __shared__ int   sI[F];
    __shared__ float sW[F];
    __shared__ float red[(EPI == 2) ? F : 1];
    int r = blockIdx.x, t = threadIdx.x;
    int beg = rowptr[r], end = rowptr[r + 1];
    float acc = 0.f;
    for (int base = beg; base < end; base += F) {
        int m = min(F, end - base);
        if (t < m) { int s = csrc[base + t]; sI[t] = s; sW[t] = dinv[s]; }
        __syncthreads();
        #pragma unroll 4
        for (int q = 0; q < m; q++) acc += sW[q] * X[(size_t)sI[q] * F + t];
        __syncthreads();
    }
    float dv = dinv[r];
    float v = dv * dv * X[(size_t)r * F + t] + dv * acc;
    if (EPI == 0) {
        out[(size_t)r * F + t] = v;
    } else if (EPI == 1) {
        out[(size_t)r * F + t] = fmaxf(v + bias[t], 0.f);
    } else {
        v += bias[t];
        v = v > 0.f ? v : expm1f(v);
        red[t] = v * v; __syncthreads();
        for (int s = F / 2; s > 0; s >>= 1) { if (t < s) red[t] += red[t + s]; __syncthreads(); }
        out[(size_t)r * F + t] = v / (sqrtf(red[0]) + Eps);
    }
}

__global__ void hn_k(const float* x1, const float* agg, const float* pbal, float* hn) {
    __shared__ float sh[256];
    int r = blockIdx.x, t = threadIdx.x;
    float v = (t < Din ? x1[(size_t)r * Din + t] : agg[(size_t)r * Din + (t - Din)]) * pbal[t];
    sh[t] = v * v; __syncthreads();
    for (int s = 128; s > 0; s >>= 1) { if (t < s) sh[t] += sh[t + s]; __syncthreads(); }
    float nrm = sqrtf(sh[0]);
    hn[(size_t)r * Dh + t] = v / (nrm + Eps);
}

// ---------------- NT GEMM via mma.sync bf16 (3-term split), pipelined ----------------
// C[M,Nc] = A[M,Kk] * B[Nc,Kk]^T, 128x128 tiles, grid (Nc/128, M/128).
// sym: compute upper tiles only, mirror via smem transpose.
// FUSE: no C write; gs[r] += sum_j fexp(5*c_rj), gdiag[r] = fexp(5*c_rr).
template<bool FUSE>
__global__ __launch_bounds__(256)
void mma_nt_k(const float* __restrict__ A, const float* __restrict__ B,
              float* __restrict__ C, float* __restrict__ gs,
              float* __restrict__ gdiag, int Kk, int Nc, int sym) {
    __shared__ __align__(16) uint32_t SB[4][128][20];
    __shared__ float rowsum[128];
    uint32_t (*AHI)[20] = SB[0];
    uint32_t (*ALO)[20] = SB[1];
    uint32_t (*BHI)[20] = SB[2];
    uint32_t (*BLO)[20] = SB[3];

    int bx = blockIdx.x, by = blockIdx.y;
    if (sym && by > bx) return;
    int brow = by * 128, bcol = bx * 128;
    int tid = threadIdx.x;
    int lane = tid & 31, wid = tid >> 5;
    int g = lane >> 2, tg = lane & 3;
    int wm = (wid >> 1) * 32, wn = (wid & 1) * 64;

    float acc[2][8][4];
    #pragma unroll
    for (int mt = 0; mt < 2; mt++)
        #pragma unroll
        for (int nt = 0; nt < 8; nt++)
            #pragma unroll
            for (int q = 0; q < 4; q++) acc[mt][nt][q] = 0.f;

    int nch = Kk >> 5;
    float4 pa[4], pb[4];
    #pragma unroll
    for (int l = 0; l < 4; l++) {
        int idx = tid + l * 256;
        int row = idx >> 3, q = idx & 7;
        pa[l] = *(const float4*)(A + (size_t)(brow + row) * Kk + q * 4);
        pb[l] = *(const float4*)(B + (size_t)(bcol + row) * Kk + q * 4);
    }

    for (int c = 0; c < nch; c++) {
        __syncthreads();
        #pragma unroll
        for (int l = 0; l < 4; l++) {
            int idx = tid + l * 256;
            int row = idx >> 3, q = idx & 7;
            float4 v = pa[l];
            uint32_t h0 = pack2(v.x, v.y), h1 = pack2(v.z, v.w);
            float ex = __uint_as_float(h0 << 16);
            float ox = __uint_as_float(h0 & 0xffff0000u);
            float ez = __uint_as_float(h1 << 16);
            float ow = __uint_as_float(h1 & 0xffff0000u);
            *(uint2*)&AHI[row][q * 2] = make_uint2(h0, h1);
            *(uint2*)&ALO[row][q * 2] = make_uint2(pack2(v.x - ex, v.y - ox),
                                                   pack2(v.z - ez, v.w - ow));
            v = pb[l];
            h0 = pack2(v.x, v.y); h1 = pack2(v.z, v.w);
            ex = __uint_as_float(h0 << 16);
            ox = __uint_as_float(h0 & 0xffff0000u);
            ez = __uint_as_float(h1 << 16);
            ow = __uint_as_float(h1 & 0xffff0000u);
            *(uint2*)&BHI[row][q * 2] = make_uint2(h0, h1);
            *(uint2*)&BLO[row][q * 2] = make_uint2(pack2(v.x - ex, v.y - ox),
                                                   pack2(v.z - ez, v.w - ow));
        }
        __syncthreads();
        if (c + 1 < nch) {
            int k0 = (c + 1) * 32;
            #pragma unroll
            for (int l = 0; l < 4; l++) {
                int idx = tid + l * 256;
                int row = idx >> 3, q = idx & 7;
                pa[l] = *(const float4*)(A + (size_t)(brow + row) * Kk + k0 + q * 4);
                pb[l] = *(const float4*)(B + (size_t)(bcol + row) * Kk + k0 + q * 4);
            }
        }
        #pragma unroll
        for (int s2 = 0; s2 < 2; s2++) {
            int kb = s2 * 8;
            uint32_t ahi[2][4], alo[2][4];
            #pragma unroll
            for (int mt = 0; mt < 2; mt++) {
                int rb = wm + mt * 16;
                ahi[mt][0] = AHI[rb + g][kb + tg];
                ahi[mt][1] = AHI[rb + g + 8][kb + tg];
                ahi[mt][2] = AHI[rb + g][kb + tg + 4];
                ahi[mt][3] = AHI[rb + g + 8][kb + tg + 4];
                alo[mt][0] = ALO[rb + g][kb + tg];
                alo[mt][1] = ALO[rb + g + 8][kb + tg];
                alo[mt][2] = ALO[rb + g][kb + tg + 4];
                alo[mt][3] = ALO[rb + g + 8][kb + tg + 4];
            }
            #pragma unroll
            for (int nh = 0; nh < 2; nh++) {
                uint32_t bhi[4][2], blo[4][2];
                #pragma unroll
                for (int n4 = 0; n4 < 4; n4++) {
                    int cb = wn + (nh * 4 + n4) * 8;
                    bhi[n4][0] = BHI[cb + g][kb + tg];
                    bhi[n4][1] = BHI[cb + g][kb + tg + 4];
                    blo[n4][0] = BLO[cb + g][kb + tg];
                    blo[n4][1] = BLO[cb + g][kb + tg + 4];
                }
                #pragma unroll
                for (int mt = 0; mt < 2; mt++)
                    #pragma unroll
                    for (int n4 = 0; n4 < 4; n4++) {
                        float* cc = acc[mt][nh * 4 + n4];
                        mma_bf16(cc, ahi[mt], bhi[n4]);
                        mma_bf16(cc, ahi[mt], blo[n4]);
                        mma_bf16(cc, alo[mt], bhi[n4]);
                    }
            }
        }
    }

    if (!FUSE) {
        #pragma unroll
        for (int mt = 0; mt < 2; mt++)
            #pragma unroll
            for (int nt = 0; nt < 8; nt++) {
                int r0 = brow + wm + mt * 16 + g;
                int c0 = bcol + wn + nt * 8 + 2 * tg;
                *(float2*)(C + (size_t)r0 * Nc + c0)       = make_float2(acc[mt][nt][0], acc[mt][nt][1]);
                *(float2*)(C + (size_t)(r0 + 8) * Nc + c0) = make_float2(acc[mt][nt][2], acc[mt][nt][3]);
            }
        if (sym && bx != by) {
            // coalesced mirror via smem transpose (reuse operand smem)
            float (*Tb)[130] = (float(*)[130])SB;     // 64 x 130 floats
            #pragma unroll
            for (int h = 0; h < 2; h++) {
                __syncthreads();
                if ((wid & 1) == h) {
                    #pragma unroll
                    for (int mt = 0; mt < 2; mt++)
                        #pragma unroll
                        for (int nt = 0; nt < 8; nt++) {
                            int rr = wm + mt * 16 + g;
                            int cl = nt * 8 + 2 * tg;
                            Tb[cl][rr]         = acc[mt][nt][0];
                            Tb[cl + 1][rr]     = acc[mt][nt][1];
                            Tb[cl][rr + 8]     = acc[mt][nt][2];
                            Tb[cl + 1][rr + 8] = acc[mt][nt][3];
                        }
                }
                __syncthreads();
                #pragma unroll
                for (int it = 0; it < 8; it++) {
                    int idx = tid + it * 256;
                    int rloc = idx >> 5, q = idx & 31;
                    float4 v = make_float4(Tb[rloc][4 * q], Tb[rloc][4 * q + 1],
                                           Tb[rloc][4 * q + 2], Tb[rloc][4 * q + 3]);
                    *(float4*)(C + (size_t)(bcol + h * 64 + rloc) * Nc + brow + 4 * q) = v;
                }
            }
        }
    } else {
        if (tid < 128) rowsum[tid] = 0.f;
        __syncthreads();
        #pragma unroll
        for (int mt = 0; mt < 2; mt++) {
            int lr0 = wm + mt * 16 + g;
            int gr0 = brow + lr0;
            float rs0 = 0.f, rs1 = 0.f;
            #pragma unroll
            for (int nt = 0; nt < 8; nt++) {
                int gc = bcol + wn + nt * 8 + 2 * tg;
                float e0 = fexp(InvT * acc[mt][nt][0]);
                float e1 = fexp(InvT * acc[mt][nt][1]);
                float e2 = fexp(InvT * acc[mt][nt][2]);
                float e3 = fexp(InvT * acc[mt][nt][3]);
                rs0 += e0 + e1;
                rs1 += e2 + e3;
                if (gc == gr0)         gdiag[gr0] = e0;
                if (gc + 1 == gr0)     gdiag[gr0] = e1;
                if (gc == gr0 + 8)     gdiag[gr0 + 8] = e2;
                if (gc + 1 == gr0 + 8) gdiag[gr0 + 8] = e3;
            }
            rs0 += __shfl_xor_sync(0xffffffffu, rs0, 1);
            rs0 += __shfl_xor_sync(0xffffffffu, rs0, 2);
            rs1 += __shfl_xor_sync(0xffffffffu, rs1, 1);
            rs1 += __shfl_xor_sync(0xffffffffu, rs1, 2);
            if (tg == 0) {
                atomicAdd(&rowsum[lr0], rs0);
                atomicAdd(&rowsum[lr0 + 8], rs1);
            }
        }
        __syncthreads();
        if (tid < 128) atomicAdd(&gs[brow + tid], rowsum[tid]);
    }
}

// ---------------- top-k (iterative argmax with cached local maxima) ----------------
__global__ void topk_k(const float* __restrict__ sim, int* topi, float* topv) {
    __shared__ float sv[Nv];
    __shared__ float lv[256];
    __shared__ int   li[256];
    __shared__ float wv[8];
    __shared__ int   wi[8];
    int r = blockIdx.x, t = threadIdx.x;
    float best = -1e30f; int besti = 1 << 30;
    #pragma unroll
    for (int q = 0; q < 16; q++) {
        int i = t + q * 256;
        float v = sim[(size_t)r * Nv + i];
        sv[i] = v;
        if (v > best) { best = v; besti = i; }   // ascending i -> first occurrence wins ties
    }
    lv[t] = best; li[t] = besti;
    __syncthreads();
    for (int k = 0; k < Kp; k++) {
        float b = lv[t]; int bi = li[t];
        #pragma unroll
        for (int o = 16; o > 0; o >>= 1) {
            float ov = __shfl_down_sync(0xffffffffu, b, o);
            int   oi = __shfl_down_sync(0xffffffffu, bi, o);
            if (ov > b || (ov == b && oi < bi)) { b = ov; bi = oi; }
        }
        if ((t & 31) == 0) { wv[t >> 5] = b; wi[t >> 5] = bi; }
        __syncthreads();
        if (t == 0) {
            float bb = wv[0]; int bj = wi[0];
            #pragma unroll
            for (int w = 1; w < 8; w++)
                if (wv[w] > bb || (wv[w] == bb && wi[w] < bj)) { bb = wv[w]; bj = wi[w]; }
            topv[r * Kp + k] = bb;
            topi[r * Kp + k] = bj;
            sv[bj] = -1e30f;
            wi[0] = bj;                       // broadcast winner
        }
        __syncthreads();
        int bj = wi[0];
        if ((bj & 255) == t) {                // owner rescans its 16 elements
            float nb = -1e30f; int ni = 1 << 30;
            #pragma unroll
            for (int q = 0; q < 16; q++) {
                int i = t + q * 256;
                float v = sv[i];
                if (v > nb) { nb = v; ni = i; }
            }
            lv[t] = nb; li[t] = ni;
        }
        __syncthreads();
    }
}

// ---------------- hash-based symmetric Wund construction ----------------
__global__ void hash_init_k(int* hkey, float* hsum, int* hcnt, int* deg2, int* nnz) {
    int i = blockIdx.x * blockDim.x + threadIdx.x;
    if (i < HCAP) { hkey[i] = -1; hsum[i] = 0.f; hcnt[i] = 0; }
    if (i < Nv) deg2[i] = 0;
    if (i == 0) nnz[0] = 0;
}

__global__ void hash_ins_k(const int* ti, const float* tv,
                           int* hkey, float* hsum, int* hcnt) {
    int e = blockIdx.x * blockDim.x + threadIdx.x;
    if (e >= Nv * Kp) return;
    int r = e / Kp, c = ti[e];
    float v = tv[e];
    if (v != v) v = 0.f;                      // nan_to_num
    int i = min(r, c), j = max(r, c);
    int key = (i << 12) | j;
    uint32_t slot = ((uint32_t)key * 2654435761u) >> 14;
    slot &= (HCAP - 1);
    while (true) {
        int old = atomicCAS(&hkey[slot], -1, key);
        if (old == -1 || old == key) break;
        slot = (slot + 1) & (HCAP - 1);
    }
    atomicAdd(&hsum[slot], v);
    atomicAdd(&hcnt[slot], 1);
}

__global__ void hash_emit_k(const int* hkey, const float* hsum, const int* hcnt,
                            int* cooi, int* cooj, float* coow, int* nnz, int* deg2) {
    int s = blockIdx.x * blockDim.x + threadIdx.x;
    if (s >= HCAP) return;
    int key = hkey[s];
    if (key < 0) return;
    float o = hsum[s] / (float)hcnt[s];
    if (o <= 0.f) return;                     // relu
    int i = key >> 12, j = key & 4095;
    int p = atomicAdd(nnz, 1);
    cooi[p] = i; cooj[p] = j; coow[p] = o;
    atomicAdd(&deg2[i], 1);
    if (i != j) atomicAdd(&deg2[j], 1);
}

__global__ void scan2_k(const int* deg2, int* rowptr, int* fill) {
    __shared__ int s[1024];
    int t = threadIdx.x;
    int c[4]; int loc = 0;
    #pragma unroll
    for (int q = 0; q < 4; q++) { c[q] = deg2[t * 4 + q]; loc += c[q]; }
    s[t] = loc; __syncthreads();
    for (int off = 1; off < 1024; off <<= 1) {
        int v = (t >= off) ? s[t - off] : 0;
        __syncthreads();
        s[t] += v;
        __syncthreads();
    }
    int run = s[t] - loc;
    #pragma unroll
    for (int q = 0; q < 4; q++) {
        rowptr[t * 4 + q] = run; run += c[q];
        fill[t * 4 + q] = 0;
    }
    if (t == 1023) rowptr[Nv] = run;
}

__global__ void fill2_k(const int* cooi, const int* cooj, const float* coow,
                        const int* nnz, const int* rowptr, int* fill,
                        int* col2, float* w2) {
    int e = blockIdx.x * blockDim.x + threadIdx.x;
    if (e >= *nnz) return;
    int i = cooi[e], j = cooj[e];
    float o = coow[e];
    int p = rowptr[i] + atomicAdd(&fill[i], 1);
    col2[p] = j; w2[p] = o;
    if (i != j) {
        p = rowptr[j] + atomicAdd(&fill[j], 1);
        col2[p] = i; w2[p] = o;
    }
}

// ---------------- CSR SpMM for Wund (gathers, fused epilogues) ----------------
template<int EPI>
__global__ void spmm_csr_k(const int* __restrict__ rowptr, const int* __restrict__ col2,
                           const float* __restrict__ w2, const float* __restrict__ X,
                           const float* __restrict__ bias, float* __restrict__ out) {
    __shared__ int   sI[256];
    __shared__ float sW[256];
    __shared__ float red[256];
    int r = blockIdx.x, t = threadIdx.x;
    int beg = rowptr[r], end = rowptr[r + 1];
    float acc = 0.f;
    for (int base = beg; base < end; base += 256) {
        int m = min(256, end - base);
        if (t < m) { sI[t] = col2[base + t]; sW[t] = w2[base + t]; }
        __syncthreads();
        #pragma unroll 4
        for (int q = 0; q < m; q++) acc += sW[q] * X[(size_t)sI[q] * Dh + t];
        __syncthreads();
    }
    float v = acc + bias[t];
    if (EPI == 1) {
        out[(size_t)r * Dh + t] = fmaxf(v, 0.f);
    } else {
        v = v > 0.f ? v : expm1f(v);
        red[t] = v * v; __syncthreads();
        for (int s = 128; s > 0; s >>= 1) { if (t < s) red[t] += red[t + s]; __syncthreads(); }
        out[(size_t)r * Dh + t] = v / (sqrtf(red[0]) + Eps);
    }
}

// ---------------- pf/pb over COO nonzeros (warp per entry) ----------------
__global__ void pfpb_k(const int* coo_i, const int* coo_j, const float* coo_w,
                       const int* nnz, const float* __restrict__ z1,
                       const float* __restrict__ z2, const float* gs,
                       float* pf, float* pb) {
    int wid = (blockIdx.x * blockDim.x + threadIdx.x) >> 5;
    int lane = threadIdx.x & 31;
    if (wid >= *nnz) return;
    int i = coo_i[wid], j = coo_j[wid];
    float wt = coo_w[wid];
    float d1 = 0.f, d2 = 0.f;
    #pragma unroll
    for (int q = 0; q < 8; q++) {
        int c = lane + q * 32;
        d1 += z1[(size_t)i * Dh + c] * z2[(size_t)j * Dh + c];
    }
    if (i != j) {
        #pragma unroll
        for (int q = 0; q < 8; q++) {
            int c = lane + q * 32;
            d2 += z1[(size_t)j * Dh + c] * z2[(size_t)i * Dh + c];
        }
    }
    #pragma unroll
    for (int o = 16; o > 0; o >>= 1) {
        d1 += __shfl_xor_sync(0xffffffffu, d1, o);
        d2 += __shfl_xor_sync(0xffffffffu, d2, o);
    }
    if (lane == 0) {
        float q1 = fexp(InvT * d1) / gs[i] * wt;
        atomicAdd(&pf[i], q1);
        atomicAdd(&pb[j], q1);
        if (i != j) {
            float q2 = fexp(InvT * d2) / gs[j] * wt;
            atomicAdd(&pf[j], q2);
            atomicAdd(&pb[i], q2);
        }
    }
}

__global__ void loss_k(const float* gdiag, const float* gs,
                       const float* pf, const float* pb, float* out) {
    __shared__ float s1[256], s2[256], s3[256];
    int t = threadIdx.x;
    float a = 0.f, b = 0.f, c = 0.f;
    for (int i = t; i < Nv; i += 256) {
        a -= logf(fmaxf(gdiag[i] / gs[i], Eps));
        b -= logf(fmaxf(pf[i], Eps));
        c -= logf(fmaxf(pb[i], Eps));
    }
    s1[t] = a; s2[t] = b; s3[t] = c; __syncthreads();
    for (int st = 128; st > 0; st >>= 1) {
        if (t < st) { s1[t] += s1[t + st]; s2[t] += s2[t + st]; s3[t] += s3[t + st]; }
        __syncthreads();
    }
    if (t == 0) out[0] = s1[0] / Nv + 0.5f * (s2[0] / Nv + s3[0] / Nv);
}

// ---------------- host launcher ----------------
extern "C" void kernel_launch(void* const* d_in, const int* in_sizes, int n_in,
                              void* d_out, int out_size) {
    const float* x       = (const float*)d_in[0];
    const int*   esrc    = (const int*)d_in[1];
    const int*   edst    = (const int*)d_in[2];
    const float* p_feat  = (const float*)d_in[3];
    const float* p_share = (const float*)d_in[4];
    const float* p_bal   = (const float*)d_in[5];
    const float* W1      = (const float*)d_in[6];
    const float* b1      = (const float*)d_in[7];
    const float* W2      = (const float*)d_in[8];
    const float* b2      = (const float*)d_in[9];
    float* out = (float*)d_out;
    int E = in_sizes[1];

    float* H = nullptr;
    cudaGetSymbolAddress((void**)&H, g_heap);
    float* sim  = H + O_SIM;
    float* x1   = H + O_X1;   float* agg  = H + O_AGG;  float* hn   = H + O_HN;
    float* xw1  = H + O_XW1;  float* bufA = H + O_BUFA; float* bufB = H + O_BUFB;
    float* z1   = H + O_Z1;   float* z2   = H + O_Z2;
    float* w1t  = H + O_W1T;  float* w2t  = H + O_W2T;
    float* deg  = H + O_DEG;  float* dinv = H + O_DINV;
    float* gs   = H + O_GS;   float* pf   = H + O_PF;   float* pb   = H + O_PB;
    float* gd   = H + O_GD;
    int*   rptr = (int*)(H + O_RPTR);
    int*   fill = (int*)(H + O_FILL);
    int*   csrc = (int*)(H + O_CSRC);
    int*   topi = (int*)(H + O_TOPI);
    float* topv = H + O_TOPV;
    int*   cooi = (int*)(H + O_COOI);
    int*   cooj = (int*)(H + O_COOJ);
    float* coow = H + O_COOW;
    int*   nnz  = (int*)(H + O_NNZ);
    int*   hkey = (int*)(H + O_HKEY);
    float* hsum = H + O_HSUM;
    int*   hcnt = (int*)(H + O_HCNT);
    int*   deg2 = (int*)(H + O_DEG2);
    int*   rpt2 = (int*)(H + O_RPT2);
    int*   fil2 = (int*)(H + O_FIL2);
    int*   col2 = (int*)(H + O_COL2);
    float* wcs2 = H + O_WCS2;

    // GCN normalization + CSR build (original graph)
    deg_init_k<<<(Nv + 255) / 256, 256>>>(deg);
    deg_count_k<<<(E + 255) / 256, 256>>>(edst, deg, E);
    dinv_k<<<(Nv + 255) / 256, 256>>>(deg, dinv);
    scan_k<<<1, 1024>>>(deg, rptr, fill);
    fill_k<<<(E + 255) / 256, 256>>>(esrc, edst, rptr, fill, csrc, E);

    // transposed weights (for NT mma GEMMs)
    transpose_k<<<dim3(Dh / 32, Din / 32), dim3(32, 32)>>>(W1, w1t, Din, Dh);
    transpose_k<<<dim3(Dh / 32, Dh / 32),  dim3(32, 32)>>>(W2, w2t, Dh, Dh);

    // prompted features + first propagate + hn
    x1_k<<<(Nv * Din) / 256, 256>>>(x, p_feat, p_share, x1);
    prop_k<Din, 0><<<Nv, Din>>>(x1, rptr, csrc, dinv, nullptr, agg);
    hn_k<<<Nv, 256>>>(x1, agg, p_bal, hn);

    // sim = hn @ hn^T, symmetric (upper tiles + coalesced mirror)
    mma_nt_k<false><<<dim3(32, 32), 256>>>(hn, hn, sim, nullptr, nullptr, Dh, Nv, 1);

    // top-(K+1) per row -> hash-symmetrized sparse Wund (COO + CSR2)
    topk_k<<<Nv, 256>>>(sim, topi, topv);
    hash_init_k<<<HCAP / 256, 256>>>(hkey, hsum, hcnt, deg2, nnz);
    hash_ins_k<<<(Nv * Kp + 255) / 256, 256>>>(topi, topv, hkey, hsum, hcnt);
    hash_emit_k<<<HCAP / 256, 256>>>(hkey, hsum, hcnt, cooi, cooj, coow, nnz, deg2);
    scan2_k<<<1, 1024>>>(deg2, rpt2, fil2);
    fill2_k<<<(Nv * Kp + 255) / 256, 256>>>(cooi, cooj, coow, nnz, rpt2, fil2, col2, wcs2);

    // xw1 = x1 @ W1 (mma)
    mma_nt_k<false><<<dim3(2, 32), 256>>>(x1, w1t, xw1, nullptr, nullptr, Din, Dh, 0);

    // view 1: sparse GCN
    prop_k<Dh, 1><<<Nv, Dh>>>(xw1, rptr, csrc, dinv, b1, bufA);
    mma_nt_k<false><<<dim3(2, 32), 256>>>(bufA, w2t, bufB, nullptr, nullptr, Dh, Dh, 0);
    prop_k<Dh, 2><<<Nv, Dh>>>(bufB, rptr, csrc, dinv, b2, z1);

    // view 2: reconstructed graph (CSR SpMM)
    spmm_csr_k<1><<<Nv, Dh>>>(rpt2, col2, wcs2, xw1, b1, bufA);
    mma_nt_k<false><<<dim3(2, 32), 256>>>(bufA, w2t, bufB, nullptr, nullptr, Dh, Dh, 0);
    spmm_csr_k<2><<<Nv, Dh>>>(rpt2, col2, wcs2, bufB, b2, z2);

    // fused z1n @ z2n^T: row exp-sums + diag
    zero_k<<<16, 256>>>(gs, (size_t)Nv * 3);
    mma_nt_k<true><<<dim3(32, 32), 256>>>(z1, z2, nullptr, gs, gd, Dh, Nv, 0);

    // pf/pb from COO nonzeros + final loss
    pfpb_k<<<COO_CAP / 8, 256>>>(cooi, cooj, coow, nnz, z1, z2, gs, pf, pb);
    loss_k<<<1, 256>>>(gd, gs, pf, pb, out);
}

// round 6
// speedup vs baseline: 3.0755x; 1.0236x over previous
#include <cuda_runtime.h>
#include <math.h>
#include <stdint.h>

// ---------------- problem constants ----------------
namespace {
constexpr int    Nv   = 4096;
constexpr int    Din  = 128;
constexpr int    Dh   = 256;
constexpr int    Kp   = 17;          // K+1
constexpr float  Eps  = 1e-8f;
constexpr float  InvT = 5.0f;        // 1/TEMP
constexpr size_t NN   = (size_t)Nv * (size_t)Nv;
constexpr int    Emax = 131072;
constexpr int    COO_CAP = 131072;
constexpr int    HCAP = 1 << 18;
constexpr int    CSR2_CAP = 160000;

// scratch heap layout (units: floats)
constexpr size_t O_SIM  = 0;
constexpr size_t O_X1   = O_SIM + NN;
constexpr size_t O_AGG  = O_X1  + (size_t)Nv*Din;
constexpr size_t O_XW1  = O_AGG + (size_t)Nv*Din;
constexpr size_t O_BUFB = O_XW1 + (size_t)Nv*Dh;
constexpr size_t O_BUFB2= O_BUFB+ (size_t)Nv*Dh;
constexpr size_t O_Z1   = O_BUFB2+(size_t)Nv*Dh;
constexpr size_t O_Z2   = O_Z1  + (size_t)Nv*Dh;
constexpr size_t O_DEG  = O_Z2  + (size_t)Nv*Dh;
constexpr size_t O_DINV = O_DEG + Nv;
constexpr size_t O_GS   = O_DINV+ Nv;
constexpr size_t O_PF   = O_GS  + Nv;
constexpr size_t O_PB   = O_PF  + Nv;
constexpr size_t O_GD   = O_PB  + Nv;
constexpr size_t O_RPTR = O_GD  + Nv;
constexpr size_t O_FILL = O_RPTR+ (Nv + 4);
constexpr size_t O_CSRC = O_FILL+ Nv;
constexpr size_t O_TOPI = O_CSRC+ Emax;
constexpr size_t O_TOPV = O_TOPI+ (size_t)Nv*Kp;
constexpr size_t O_COOI = O_TOPV+ (size_t)Nv*Kp;
constexpr size_t O_COOJ = O_COOI+ COO_CAP;
constexpr size_t O_COOW = O_COOJ+ COO_CAP;
constexpr size_t O_NNZ  = O_COOW+ COO_CAP;
constexpr size_t O_HKEY = O_NNZ + 4;
constexpr size_t O_HSUM = O_HKEY+ HCAP;
constexpr size_t O_HCNT = O_HSUM+ HCAP;
constexpr size_t O_DEG2 = O_HCNT+ HCAP;
constexpr size_t O_RPT2 = O_DEG2+ Nv;
constexpr size_t O_FIL2 = O_RPT2+ (Nv + 4);
constexpr size_t O_COL2 = O_FIL2+ Nv;
constexpr size_t O_WCS2 = O_COL2+ CSR2_CAP;
// packed bf16x2 split operands (u32 in float slots); K2 = K/2 per row
constexpr size_t O_HNH  = O_WCS2+ CSR2_CAP;            // Nv*128
constexpr size_t O_HNL  = O_HNH + (size_t)Nv*128;
constexpr size_t O_X1H  = O_HNL + (size_t)Nv*128;      // Nv*64
constexpr size_t O_X1L  = O_X1H + (size_t)Nv*64;
constexpr size_t O_BAH  = O_X1L + (size_t)Nv*64;       // Nv*128
constexpr size_t O_BAL  = O_BAH + (size_t)Nv*128;
constexpr size_t O_BA2H = O_BAL + (size_t)Nv*128;
constexpr size_t O_BA2L = O_BA2H+ (size_t)Nv*128;
constexpr size_t O_Z1H  = O_BA2L+ (size_t)Nv*128;
constexpr size_t O_Z1L  = O_Z1H + (size_t)Nv*128;
constexpr size_t O_Z2H  = O_Z1L + (size_t)Nv*128;
constexpr size_t O_Z2L  = O_Z2H + (size_t)Nv*128;
constexpr size_t O_W1TH = O_Z2L + (size_t)Nv*128;      // Dh*64
constexpr size_t O_W1TL = O_W1TH+ (size_t)Dh*64;
constexpr size_t O_W2TH = O_W1TL+ (size_t)Dh*64;       // Dh*128
constexpr size_t O_W2TL = O_W2TH+ (size_t)Dh*128;
constexpr size_t TOTAL  = O_W2TL+ (size_t)Dh*128;

constexpr unsigned SMEM_DYN = (2 * 4 * 2560 + 128) * 4;   // 2 stages x 4 arrays x 128x20 u32 + rowsum
}

__device__ __align__(256) float g_heap[TOTAL];

// ---------------- fast exp (FMA only) ----------------
__device__ __forceinline__ float fexp(float x) {
    float t  = x * 1.4426950408889634f;
    float rf = __fadd_rn(t, 12582912.0f);
    int   e  = __float_as_int(rf) - 0x4B400000;
    float r  = __fadd_rn(rf, -12582912.0f);
    float f  = t - r;
    float p  = fmaf(1.5403530394e-4f, f, 1.3333558146e-3f);
    p = fmaf(p, f, 9.6181291076e-3f);
    p = fmaf(p, f, 5.5504108665e-2f);
    p = fmaf(p, f, 2.4022650696e-1f);
    p = fmaf(p, f, 6.9314718056e-1f);
    p = fmaf(p, f, 1.0f);
    return __int_as_float(__float_as_int(p) + (e << 23));
}

// ---------------- bf16 split helpers ----------------
__device__ __forceinline__ uint32_t pack2(float e, float o) {
    uint32_t r;
    asm("cvt.rn.bf16x2.f32 %0, %1, %2;" : "=r"(r) : "f"(o), "f"(e));
    return r;
}
__device__ __forceinline__ void split_pair(float v0, float v1, uint32_t& hi, uint32_t& lo) {
    hi = pack2(v0, v1);
    float e = __uint_as_float(hi << 16);
    float o = __uint_as_float(hi & 0xffff0000u);
    lo = pack2(v0 - e, v1 - o);
}
__device__ __forceinline__ void mma_bf16(float* c, const uint32_t* a, const uint32_t* b) {
    asm volatile(
        "mma.sync.aligned.m16n8k16.row.col.f32.bf16.bf16.f32 "
        "{%0,%1,%2,%3}, {%4,%5,%6,%7}, {%8,%9}, {%0,%1,%2,%3};"
        : "+f"(c[0]), "+f"(c[1]), "+f"(c[2]), "+f"(c[3])
        : "r"(a[0]), "r"(a[1]), "r"(a[2]), "r"(a[3]), "r"(b[0]), "r"(b[1]));
}
__device__ __forceinline__ uint32_t smem_u32(const void* p) {
    uint32_t a;
    asm("{ .reg .u64 t; cvta.to.shared.u64 t, %1; cvt.u32.u64 %0, t; }" : "=r"(a) : "l"(p));
    return a;
}
__device__ __forceinline__ void cpa16(uint32_t dst, const void* src) {
    asm volatile("cp.async.cg.shared.global [%0], [%1], 16;" :: "r"(dst), "l"(src));
}
#define CP_COMMIT() asm volatile("cp.async.commit_group;" ::: "memory")
#define LDMX4(r0, r1, r2, r3, addr) \
    asm volatile("ldmatrix.sync.aligned.m8n8.x4.shared.b16 {%0,%1,%2,%3}, [%4];" \
        : "=r"(r0), "=r"(r1), "=r"(r2), "=r"(r3) : "r"(addr))

// ---------------- init / small kernels ----------------
__global__ void init_k(float* deg, int* hkey, float* hsum, int* hcnt,
                       int* deg2, int* nnz, float* gs3) {
    int i = blockIdx.x * blockDim.x + threadIdx.x;
    if (i < HCAP) { hkey[i] = -1; hsum[i] = 0.f; hcnt[i] = 0; }
    if (i < Nv) { deg[i] = 1.f; deg2[i] = 0; }
    if (i < Nv * 3) gs3[i] = 0.f;
    if (i == 0) nnz[0] = 0;
}
__global__ void deg_count_k(const int* dst, float* deg, int E) {
    int e = blockIdx.x * blockDim.x + threadIdx.x;
    if (e < E) atomicAdd(&deg[dst[e]], 1.f);
}

__global__ void x1_k(const float* x, const float* pf, const float* ps,
                     float* x1, uint32_t* x1h, uint32_t* x1l) {
    int i = blockIdx.x * blockDim.x + threadIdx.x;   // pair index
    if (i >= Nv * 64) return;
    int row = i >> 6, p = i & 63;
    int c0 = 2 * p, c1 = c0 + 1;
    float a0 = x[(size_t)row * Din + c0], a1 = x[(size_t)row * Din + c1];
    float v0 = fmaxf(a0 * pf[c0], 0.f) * ps[c0];
    float v1 = fmaxf(a1 * pf[c1], 0.f) * ps[c1];
    x1[(size_t)row * Din + c0] = v0;
    x1[(size_t)row * Din + c1] = v1;
    uint32_t hi, lo;
    split_pair(v0, v1, hi, lo);
    x1h[i] = hi; x1l[i] = lo;
}

// transpose A[R rows=k][Cc cols=n] -> NT operand [n][k], emitting bf16 hi/lo pairs
__global__ void transpose_split_k(const float* __restrict__ A,
                                  uint32_t* __restrict__ th, uint32_t* __restrict__ tl,
                                  int R, int Cc) {
    __shared__ float tile[32][33];
    int x = blockIdx.x * 32 + threadIdx.x;
    int y = blockIdx.y * 32 + threadIdx.y;
    tile[threadIdx.y][threadIdx.x] = A[(size_t)y * Cc + x];
    __syncthreads();
    if (threadIdx.x & 1) return;
    int xo = blockIdx.y * 32 + threadIdx.x;   // k index (even)
    int yo = blockIdx.x * 32 + threadIdx.y;   // n index
    float v0 = tile[threadIdx.x][threadIdx.y];
    float v1 = tile[threadIdx.x + 1][threadIdx.y];
    uint32_t hi, lo;
    split_pair(v0, v1, hi, lo);
    size_t idx = ((size_t)yo * R + xo) >> 1;
    th[idx] = hi; tl[idx] = lo;
}

// ---------------- CSR build (original graph); dinv fused into scan ----------------
__global__ void scan_k(const float* deg, float* dinv, int* rowptr, int* fill) {
    __shared__ int s[1024];
    int t = threadIdx.x;
    int c[4]; int loc = 0;
    #pragma unroll
    for (int q = 0; q < 4; q++) {
        float d = deg[t * 4 + q];
        dinv[t * 4 + q] = rsqrtf(d);
        c[q] = (int)d - 1; loc += c[q];
    }
    s[t] = loc; __syncthreads();
    for (int off = 1; off < 1024; off <<= 1) {
        int v = (t >= off) ? s[t - off] : 0;
        __syncthreads();
        s[t] += v;
        __syncthreads();
    }
    int run = s[t] - loc;
    #pragma unroll
    for (int q = 0; q < 4; q++) {
        rowptr[t * 4 + q] = run; run += c[q];
        fill[t * 4 + q] = 0;
    }
    if (t == 1023) rowptr[Nv] = run;
}

__global__ void fill_k(const int* es, const int* ed, const int* rowptr,
                       int* fill, int* csrc, int E) {
    int e = blockIdx.x * blockDim.x + threadIdx.x;
    if (e >= E) return;
    int d = ed[e];
    int p = rowptr[d] + atomicAdd(&fill[d], 1);
    csrc[p] = es[e];
}

// ---------------- CSR gather propagate ----------------
// EPI 0: f32 only. EPI 1: relu -> split only. EPI 2: elu+norm -> f32 + split.
template<int F, int EPI>
__global__ void prop_k(const float* __restrict__ X, const int* __restrict__ rowptr,
                       const int* __restrict__ csrc, const float* __restrict__ dinv,
                       const float* __restrict__ bias, float* __restrict__ outF,
                       uint32_t* __restrict__ outH, uint32_t* __restrict__ outL) {
    __shared__ int   sI[F];
    __shared__ float sW[F];
    __shared__ float red[F];
    int r = blockIdx.x, t = threadIdx.x;
    int beg = rowptr[r], end = rowptr[r + 1];
    float acc = 0.f;
    for (int base = beg; base < end; base += F) {
        int m = min(F, end - base);
        if (t < m) { int s = csrc[base + t]; sI[t] = s; sW[t] = dinv[s]; }
        __syncthreads();
        #pragma unroll 4
        for (int q = 0; q < m; q++) acc += sW[q] * X[(size_t)sI[q] * F + t];
        __syncthreads();
    }
    float dv = dinv[r];
    float v = dv * dv * X[(size_t)r * F + t] + dv * acc;
    if (EPI == 0) {
        outF[(size_t)r * F + t] = v;
        return;
    }
    if (EPI == 1) {
        v = fmaxf(v + bias[t], 0.f);
    } else {
        v += bias[t];
        v = v > 0.f ? v : expm1f(v);
        red[t] = v * v; __syncthreads();
        for (int s = F / 2; s > 0; s >>= 1) { if (t < s) red[t] += red[t + s]; __syncthreads(); }
        v = v / (sqrtf(red[0]) + Eps);
        outF[(size_t)r * F + t] = v;
        __syncthreads();
    }
    red[t] = v; __syncthreads();
    if (t < F / 2) {
        uint32_t hi, lo;
        split_pair(red[2 * t], red[2 * t + 1], hi, lo);
        outH[(size_t)r * (F / 2) + t] = hi;
        outL[(size_t)r * (F / 2) + t] = lo;
    }
}

// hn (normalized prompt-balanced concat) -> split only
__global__ void hn_k(const float* x1, const float* agg, const float* pbal,
                     uint32_t* hnh, uint32_t* hnl) {
    __shared__ float sh[256];
    __shared__ float sv[256];
    int r = blockIdx.x, t = threadIdx.x;
    float v = (t < Din ? x1[(size_t)r * Din + t] : agg[(size_t)r * Din + (t - Din)]) * pbal[t];
    sh[t] = v * v; __syncthreads();
    for (int s = 128; s > 0; s >>= 1) { if (t < s) sh[t] += sh[t + s]; __syncthreads(); }
    float vn = v / (sqrtf(sh[0]) + Eps);
    sv[t] = vn; __syncthreads();
    if (t < 128) {
        uint32_t hi, lo;
        split_pair(sv[2 * t], sv[2 * t + 1], hi, lo);
        hnh[(size_t)r * 128 + t] = hi;
        hnl[(size_t)r * 128 + t] = lo;
    }
}

// ---------------- NT GEMM: pre-split bf16 operands, cp.async double buffer, ldmatrix ----------------
// C[M,Nc] = A * B^T over Kk. grid (Nc/128, M/128, batch). z==1 -> A2/C2.
template<bool FUSE>
__global__ __launch_bounds__(256)
void mma_nt_k(const uint32_t* __restrict__ Ahi, const uint32_t* __restrict__ Alo,
              const uint32_t* __restrict__ A2hi, const uint32_t* __restrict__ A2lo,
              const uint32_t* __restrict__ Bhi, const uint32_t* __restrict__ Blo,
              float* C, float* C2, float* __restrict__ gs, float* __restrict__ gdiag,
              int Kk, int Nc, int sym) {
    extern __shared__ uint32_t dsm[];
    float* rowsum = (float*)(dsm + 2 * 4 * 2560);

    int bx = blockIdx.x, by = blockIdx.y;
    if (sym && by > bx) return;
    if (blockIdx.z == 1) { Ahi = A2hi; Alo = A2lo; C = C2; }
    int brow = by * 128, bcol = bx * 128;
    int tid = threadIdx.x;
    int lane = tid & 31, wid = tid >> 5;
    int g = lane >> 2, tg = lane & 3;
    int lrow = lane & 7, part = lane >> 3;
    int wm = (wid >> 1) * 32, wn = (wid & 1) * 64;
    int K2 = Kk >> 1;
    int nch = Kk >> 5;
    uint32_t smb = smem_u32(dsm);

    const uint32_t* gA[2] = {Ahi, Alo};
    const uint32_t* gB[2] = {Bhi, Blo};

    auto issue = [&](int st, int c) {
        #pragma unroll
        for (int l = 0; l < 8; l++) {
            int arr = l >> 1;                         // 0:Ahi 1:Alo 2:Bhi 3:Blo
            int rem = ((l & 1) << 8) + tid;           // 0..511
            int row = rem >> 2, seg = rem & 3;
            const uint32_t* gbase = (arr < 2) ? gA[arr] : gB[arr - 2];
            int rb = (arr < 2) ? brow : bcol;
            const uint32_t* src = gbase + (size_t)(rb + row) * K2 + c * 16 + seg * 4;
            uint32_t dst = smb + ((st * 4 + arr) * 2560 + row * 20 + seg * 4) * 4;
            cpa16(dst, src);
        }
        CP_COMMIT();
    };

    float acc[2][8][4];
    #pragma unroll
    for (int mt = 0; mt < 2; mt++)
        #pragma unroll
        for (int nt = 0; nt < 8; nt++)
            #pragma unroll
            for (int q = 0; q < 4; q++) acc[mt][nt][q] = 0.f;

    issue(0, 0);
    issue(1, 1);

    for (int c = 0; c < nch; c++) {
        if (c + 1 < nch) asm volatile("cp.async.wait_group 1;" ::: "memory");
        else             asm volatile("cp.async.wait_group 0;" ::: "memory");
        __syncthreads();
        int st = c & 1;
        uint32_t bAH = smb + (st * 4 + 0) * 10240;
        uint32_t bAL = smb + (st * 4 + 1) * 10240;
        uint32_t bBH = smb + (st * 4 + 2) * 10240;
        uint32_t bBL = smb + (st * 4 + 3) * 10240;
        #pragma unroll
        for (int s2 = 0; s2 < 2; s2++) {
            int kb = s2 * 8;
            int acol = kb + (part >> 1) * 4;
            int bcolk = kb + (part & 1) * 4;
            uint32_t ahi[2][4], alo[2][4];
            #pragma unroll
            for (int mt = 0; mt < 2; mt++) {
                int arow = wm + mt * 16 + lrow + (part & 1) * 8;
                uint32_t off = (arow * 20 + acol) * 4;
                LDMX4(ahi[mt][0], ahi[mt][1], ahi[mt][2], ahi[mt][3], bAH + off);
                LDMX4(alo[mt][0], alo[mt][1], alo[mt][2], alo[mt][3], bAL + off);
            }
            #pragma unroll
            for (int np = 0; np < 4; np++) {
                int brw = wn + np * 16 + lrow + (part >> 1) * 8;
                uint32_t off = (brw * 20 + bcolk) * 4;
                uint32_t bh[4], bl[4];
                LDMX4(bh[0], bh[1], bh[2], bh[3], bBH + off);
                LDMX4(bl[0], bl[1], bl[2], bl[3], bBL + off);
                #pragma unroll
                for (int hf = 0; hf < 2; hf++) {
                    uint32_t bh2[2] = {bh[hf * 2], bh[hf * 2 + 1]};
                    uint32_t bl2[2] = {bl[hf * 2], bl[hf * 2 + 1]};
                    #pragma unroll
                    for (int mt = 0; mt < 2; mt++) {
                        float* cc = acc[mt][np * 2 + hf];
                        mma_bf16(cc, ahi[mt], bh2);
                        mma_bf16(cc, ahi[mt], bl2);
                        mma_bf16(cc, alo[mt], bh2);
                    }
                }
            }
        }
        __syncthreads();
        if (c + 2 < nch) issue(st, c + 2);
    }

    if (!FUSE) {
        #pragma unroll
        for (int mt = 0; mt < 2; mt++)
            #pragma unroll
            for (int nt = 0; nt < 8; nt++) {
                int r0 = brow + wm + mt * 16 + g;
                int c0 = bcol + wn + nt * 8 + 2 * tg;
                *(float2*)(C + (size_t)r0 * Nc + c0)       = make_float2(acc[mt][nt][0], acc[mt][nt][1]);
                *(float2*)(C + (size_t)(r0 + 8) * Nc + c0) = make_float2(acc[mt][nt][2], acc[mt][nt][3]);
            }
        if (sym && bx != by) {
            float (*Tb)[130] = (float(*)[130])dsm;    // 64 x 130 staging
            #pragma unroll
            for (int h = 0; h < 2; h++) {
                __syncthreads();
                if ((wid & 1) == h) {
                    #pragma unroll
                    for (int mt = 0; mt < 2; mt++)
                        #pragma unroll
                        for (int nt = 0; nt < 8; nt++) {
                            int rr = wm + mt * 16 + g;
                            int cl = nt * 8 + 2 * tg;
                            Tb[cl][rr]         = acc[mt][nt][0];
                            Tb[cl + 1][rr]     = acc[mt][nt][1];
                            Tb[cl][rr + 8]     = acc[mt][nt][2];
                            Tb[cl + 1][rr + 8] = acc[mt][nt][3];
                        }
                }
                __syncthreads();
                #pragma unroll
                for (int it = 0; it < 8; it++) {
                    int idx = tid + it * 256;
                    int rloc = idx >> 5, q = idx & 31;
                    float4 v = make_float4(Tb[rloc][4 * q], Tb[rloc][4 * q + 1],
                                           Tb[rloc][4 * q + 2], Tb[rloc][4 * q + 3]);
                    *(float4*)(C + (size_t)(bcol + h * 64 + rloc) * Nc + brow + 4 * q) = v;
                }
            }
        }
    } else {
        if (tid < 128) rowsum[tid] = 0.f;
        __syncthreads();
        #pragma unroll
        for (int mt = 0; mt < 2; mt++) {
            int lr0 = wm + mt * 16 + g;
            int gr0 = brow + lr0;
            float rs0 = 0.f, rs1 = 0.f;
            #pragma unroll
            for (int nt = 0; nt < 8; nt++) {
                int gc = bcol + wn + nt * 8 + 2 * tg;
                float e0 = fexp(InvT * acc[mt][nt][0]);
                float e1 = fexp(InvT * acc[mt][nt][1]);
                float e2 = fexp(InvT * acc[mt][nt][2]);
                float e3 = fexp(InvT * acc[mt][nt][3]);
                rs0 += e0 + e1;
                rs1 += e2 + e3;
                if (gc == gr0)         gdiag[gr0] = e0;
                if (gc + 1 == gr0)     gdiag[gr0] = e1;
                if (gc == gr0 + 8)     gdiag[gr0 + 8] = e2;
                if (gc + 1 == gr0 + 8) gdiag[gr0 + 8] = e3;
            }
            rs0 += __shfl_xor_sync(0xffffffffu, rs0, 1);
            rs0 += __shfl_xor_sync(0xffffffffu, rs0, 2);
            rs1 += __shfl_xor_sync(0xffffffffu, rs1, 1);
            rs1 += __shfl_xor_sync(0xffffffffu, rs1, 2);
            if (tg == 0) {
                atomicAdd(&rowsum[lr0], rs0);
                atomicAdd(&rowsum[lr0 + 8], rs1);
            }
        }
        __syncthreads();
        if (tid < 128) atomicAdd(&gs[brow + tid], rowsum[tid]);
    }
}

// ---------------- top-k (iterative argmax with cached local maxima) ----------------
__global__ void topk_k(const float* __restrict__ sim, int* topi, float* topv) {
    __shared__ float sv[Nv];
    __shared__ float lv[256];
    __shared__ int   li[256];
    __shared__ float wv[8];
    __shared__ int   wi[8];
    int r = blockIdx.x, t = threadIdx.x;
    float best = -1e30f; int besti = 1 << 30;
    #pragma unroll
    for (int q = 0; q < 16; q++) {
        int i = t + q * 256;
        float v = sim[(size_t)r * Nv + i];
        sv[i] = v;
        if (v > best) { best = v; besti = i; }
    }
    lv[t] = best; li[t] = besti;
    __syncthreads();
    for (int k = 0; k < Kp; k++) {
        float b = lv[t]; int bi = li[t];
        #pragma unroll
        for (int o = 16; o > 0; o >>= 1) {
            float ov = __shfl_down_sync(0xffffffffu, b, o);
            int   oi = __shfl_down_sync(0xffffffffu, bi, o);
            if (ov > b || (ov == b && oi < bi)) { b = ov; bi = oi; }
        }
        if ((t & 31) == 0) { wv[t >> 5] = b; wi[t >> 5] = bi; }
        __syncthreads();
        if (t == 0) {
            float bb = wv[0]; int bj = wi[0];
            #pragma unroll
            for (int w = 1; w < 8; w++)
                if (wv[w] > bb || (wv[w] == bb && wi[w] < bj)) { bb = wv[w]; bj = wi[w]; }
            topv[r * Kp + k] = bb;
            topi[r * Kp + k] = bj;
            sv[bj] = -1e30f;
            wi[0] = bj;
        }
        __syncthreads();
        int bj = wi[0];
        if ((bj & 255) == t) {
            float nb = -1e30f; int ni = 1 << 30;
            #pragma unroll
            for (int q = 0; q < 16; q++) {
                int i = t + q * 256;
                float v = sv[i];
                if (v > nb) { nb = v; ni = i; }
            }
            lv[t] = nb; li[t] = ni;
        }
        __syncthreads();
    }
}

// ---------------- hash-based symmetric Wund ----------------
__global__ void hash_ins_k(const int* ti, const float* tv,
                           int* hkey, float* hsum, int* hcnt) {
    int e = blockIdx.x * blockDim.x + threadIdx.x;
    if (e >= Nv * Kp) return;
    int r = e / Kp, c = ti[e];
    float v = tv[e];
    if (v != v) v = 0.f;
    int i = min(r, c), j = max(r, c);
    int key = (i << 12) | j;
    uint32_t slot = ((uint32_t)key * 2654435761u) >> 14;
    slot &= (HCAP - 1);
    while (true) {
        int old = atomicCAS(&hkey[slot], -1, key);
        if (old == -1 || old == key) break;
        slot = (slot + 1) & (HCAP - 1);
    }
    atomicAdd(&hsum[slot], v);
    atomicAdd(&hcnt[slot], 1);
}

__global__ void hash_emit_k(const int* hkey, const float* hsum, const int* hcnt,
                            int* cooi, int* cooj, float* coow, int* nnz, int* deg2) {
    int s = blockIdx.x * blockDim.x + threadIdx.x;
    if (s >= HCAP) return;
    int key = hkey[s];
    if (key < 0) return;
    float o = hsum[s] / (float)hcnt[s];
    if (o <= 0.f) return;
    int i = key >> 12, j = key & 4095;
    int p = atomicAdd(nnz, 1);
    cooi[p] = i; cooj[p] = j; coow[p] = o;
    atomicAdd(&deg2[i], 1);
    if (i != j) atomicAdd(&deg2[j], 1);
}

__global__ void scan2_k(const int* deg2, int* rowptr, int* fill) {
    __shared__ int s[1024];
    int t = threadIdx.x;
    int c[4]; int loc = 0;
    #pragma unroll
    for (int q = 0; q < 4; q++) { c[q] = deg2[t * 4 + q]; loc += c[q]; }
    s[t] = loc; __syncthreads();
    for (int off = 1; off < 1024; off <<= 1) {
        int v = (t >= off) ? s[t - off] : 0;
        __syncthreads();
        s[t] += v;
        __syncthreads();
    }
    int run = s[t] - loc;
    #pragma unroll
    for (int q = 0; q < 4; q++) {
        rowptr[t * 4 + q] = run; run += c[q];
        fill[t * 4 + q] = 0;
    }
    if (t == 1023) rowptr[Nv] = run;
}

__global__ void fill2_k(const int* cooi, const int* cooj, const float* coow,
                        const int* nnz, const int* rowptr, int* fill,
                        int* col2, float* w2) {
    int e = blockIdx.x * blockDim.x + threadIdx.x;
    if (e >= *nnz) return;
    int i = cooi[e], j = cooj[e];
    float o = coow[e];
    int p = rowptr[i] + atomicAdd(&fill[i], 1);
    col2[p] = j; w2[p] = o;
    if (i != j) {
        p = rowptr[j] + atomicAdd(&fill[j], 1);
        col2[p] = i; w2[p] = o;
    }
}

// ---------------- CSR SpMM for Wund ----------------
template<int EPI>
__global__ void spmm_csr_k(const int* __restrict__ rowptr, const int* __restrict__ col2,
                           const float* __restrict__ w2, const float* __restrict__ X,
                           const float* __restrict__ bias, float* __restrict__ outF,
                           uint32_t* __restrict__ outH, uint32_t* __restrict__ outL) {
    __shared__ int   sI[256];
    __shared__ float sW[256];
    __shared__ float red[256];
    int r = blockIdx.x, t = threadIdx.x;
    int beg = rowptr[r], end = rowptr[r + 1];
    float acc = 0.f;
    for (int base = beg; base < end; base += 256) {
        int m = min(256, end - base);
        if (t < m) { sI[t] = col2[base + t]; sW[t] = w2[base + t]; }
        __syncthreads();
        #pragma unroll 4
        for (int q = 0; q < m; q++) acc += sW[q] * X[(size_t)sI[q] * Dh + t];
        __syncthreads();
    }
    float v = acc + bias[t];
    if (EPI == 1) {
        v = fmaxf(v, 0.f);
    } else {
        v = v > 0.f ? v : expm1f(v);
        red[t] = v * v; __syncthreads();
        for (int s = 128; s > 0; s >>= 1) { if (t < s) red[t] += red[t + s]; __syncthreads(); }
        v = v / (sqrtf(red[0]) + Eps);
        outF[(size_t)r * Dh + t] = v;
        __syncthreads();
    }
    red[t] = v; __syncthreads();
    if (t < 128) {
        uint32_t hi, lo;
        split_pair(red[2 * t], red[2 * t + 1], hi, lo);
        outH[(size_t)r * 128 + t] = hi;
        outL[(size_t)r * 128 + t] = lo;
    }
}

// ---------------- pf/pb over COO nonzeros ----------------
__global__ void pfpb_k(const int* coo_i, const int* coo_j, const float* coo_w,
                       const int* nnz, const float* __restrict__ z1,
                       const float* __restrict__ z2, const float* gs,
                       float* pf, float* pb) {
    int wid = (blockIdx.x * blockDim.x + threadIdx.x) >> 5;
    int lane = threadIdx.x & 31;
    if (wid >= *nnz) return;
    int i = coo_i[wid], j = coo_j[wid];
    float wt = coo_w[wid];
    float d1 = 0.f, d2 = 0.f;
    #pragma unroll
    for (int q = 0; q < 8; q++) {
        int c = lane + q * 32;
        d1 += z1[(size_t)i * Dh + c] * z2[(size_t)j * Dh + c];
    }
    if (i != j) {
        #pragma unroll
        for (int q = 0; q < 8; q++) {
            int c = lane + q * 32;
            d2 += z1[(size_t)j * Dh + c] * z2[(size_t)i * Dh + c];
        }
    }
    #pragma unroll
    for (int o = 16; o > 0; o >>= 1) {
        d1 += __shfl_xor_sync(0xffffffffu, d1, o);
        d2 += __shfl_xor_sync(0xffffffffu, d2, o);
    }
    if (lane == 0) {
        float q1 = fexp(InvT * d1) / gs[i] * wt;
        atomicAdd(&pf[i], q1);
        atomicAdd(&pb[j], q1);
        if (i != j) {
            float q2 = fexp(InvT * d2) / gs[j] * wt;
            atomicAdd(&pf[j], q2);
            atomicAdd(&pb[i], q2);
        }
    }
}

__global__ void loss_k(const float* gdiag, const float* gs,
                       const float* pf, const float* pb, float* out) {
    __shared__ float s1[256], s2[256], s3[256];
    int t = threadIdx.x;
    float a = 0.f, b = 0.f, c = 0.f;
    for (int i = t; i < Nv; i += 256) {
        a -= logf(fmaxf(gdiag[i] / gs[i], Eps));
        b -= logf(fmaxf(pf[i], Eps));
        c -= logf(fmaxf(pb[i], Eps));
    }
    s1[t] = a; s2[t] = b; s3[t] = c; __syncthreads();
    for (int st = 128; st > 0; st >>= 1) {
        if (t < st) { s1[t] += s1[t + st]; s2[t] += s2[t + st]; s3[t] += s3[t + st]; }
        __syncthreads();
    }
    if (t == 0) out[0] = s1[0] / Nv + 0.5f * (s2[0] / Nv + s3[0] / Nv);
}

// ---------------- host launcher ----------------
extern "C" void kernel_launch(void* const* d_in, const int* in_sizes, int n_in,
                              void* d_out, int out_size) {
    const float* x       = (const float*)d_in[0];
    const int*   esrc    = (const int*)d_in[1];
    const int*   edst    = (const int*)d_in[2];
    const float* p_feat  = (const float*)d_in[3];
    const float* p_share = (const float*)d_in[4];
    const float* p_bal   = (const float*)d_in[5];
    const float* W1      = (const float*)d_in[6];
    const float* b1      = (const float*)d_in[7];
    const float* W2      = (const float*)d_in[8];
    const float* b2      = (const float*)d_in[9];
    float* out = (float*)d_out;
    int E = in_sizes[1];

    float* H = nullptr;
    cudaGetSymbolAddress((void**)&H, g_heap);
    float* sim  = H + O_SIM;
    float* x1   = H + O_X1;   float* agg  = H + O_AGG;
    float* xw1  = H + O_XW1;  float* bufB = H + O_BUFB; float* bufB2 = H + O_BUFB2;
    float* z1   = H + O_Z1;   float* z2   = H + O_Z2;
    float* deg  = H + O_DEG;  float* dinv = H + O_DINV;
    float* gs   = H + O_GS;   float* pf   = H + O_PF;   float* pb   = H + O_PB;
    float* gd   = H + O_GD;
    int*   rptr = (int*)(H + O_RPTR);
    int*   fill = (int*)(H + O_FILL);
    int*   csrc = (int*)(H + O_CSRC);
    int*   topi = (int*)(H + O_TOPI);
    float* topv = H + O_TOPV;
    int*   cooi = (int*)(H + O_COOI);
    int*   cooj = (int*)(H + O_COOJ);
    float* coow = H + O_COOW;
    int*   nnz  = (int*)(H + O_NNZ);
    int*   hkey = (int*)(H + O_HKEY);
    float* hsum = H + O_HSUM;
    int*   hcnt = (int*)(H + O_HCNT);
    int*   deg2 = (int*)(H + O_DEG2);
    int*   rpt2 = (int*)(H + O_RPT2);
    int*   fil2 = (int*)(H + O_FIL2);
    int*   col2 = (int*)(H + O_COL2);
    float* wcs2 = H + O_WCS2;
    uint32_t* hnh  = (uint32_t*)(H + O_HNH);  uint32_t* hnl  = (uint32_t*)(H + O_HNL);
    uint32_t* x1h  = (uint32_t*)(H + O_X1H);  uint32_t* x1l  = (uint32_t*)(H + O_X1L);
    uint32_t* bah  = (uint32_t*)(H + O_BAH);  uint32_t* bal  = (uint32_t*)(H + O_BAL);
    uint32_t* ba2h = (uint32_t*)(H + O_BA2H); uint32_t* ba2l = (uint32_t*)(H + O_BA2L);
    uint32_t* z1h  = (uint32_t*)(H + O_Z1H);  uint32_t* z1l  = (uint32_t*)(H + O_Z1L);
    uint32_t* z2h  = (uint32_t*)(H + O_Z2H);  uint32_t* z2l  = (uint32_t*)(H + O_Z2L);
    uint32_t* w1th = (uint32_t*)(H + O_W1TH); uint32_t* w1tl = (uint32_t*)(H + O_W1TL);
    uint32_t* w2th = (uint32_t*)(H + O_W2TH); uint32_t* w2tl = (uint32_t*)(H + O_W2TL);

    cudaFuncSetAttribute(mma_nt_k<false>, cudaFuncAttributeMaxDynamicSharedMemorySize, SMEM_DYN);
    cudaFuncSetAttribute(mma_nt_k<true>,  cudaFuncAttributeMaxDynamicSharedMemorySize, SMEM_DYN);

    // init + CSR (original graph) + weight splits
    init_k<<<HCAP / 256, 256>>>(deg, hkey, hsum, hcnt, deg2, nnz, gs);
    deg_count_k<<<(E + 255) / 256, 256>>>(edst, deg, E);
    scan_k<<<1, 1024>>>(deg, dinv, rptr, fill);
    fill_k<<<(E + 255) / 256, 256>>>(esrc, edst, rptr, fill, csrc, E);
    transpose_split_k<<<dim3(Dh / 32, Din / 32), dim3(32, 32)>>>(W1, w1th, w1tl, Din, Dh);
    transpose_split_k<<<dim3(Dh / 32, Dh / 32),  dim3(32, 32)>>>(W2, w2th, w2tl, Dh, Dh);

    // prompted features (+split), xw1 GEMM, first propagate, hn
    x1_k<<<(Nv * 64) / 256, 256>>>(x, p_feat, p_share, x1, x1h, x1l);
    mma_nt_k<false><<<dim3(2, 32, 1), 256, SMEM_DYN>>>(
        x1h, x1l, nullptr, nullptr, w1th, w1tl, xw1, nullptr, nullptr, nullptr, Din, Dh, 0);
    prop_k<Din, 0><<<Nv, Din>>>(x1, rptr, csrc, dinv, nullptr, agg, nullptr, nullptr);
    hn_k<<<Nv, 256>>>(x1, agg, p_bal, hnh, hnl);

    // sim = hn @ hn^T (symmetric)
    mma_nt_k<false><<<dim3(32, 32, 1), 256, SMEM_DYN>>>(
        hnh, hnl, nullptr, nullptr, hnh, hnl, sim, nullptr, nullptr, nullptr, Dh, Nv, 1);

    // top-k -> hash -> CSR2
    topk_k<<<Nv, 256>>>(sim, topi, topv);
    hash_ins_k<<<(Nv * Kp + 255) / 256, 256>>>(topi, topv, hkey, hsum, hcnt);
    hash_emit_k<<<HCAP / 256, 256>>>(hkey, hsum, hcnt, cooi, cooj, coow, nnz, deg2);
    scan2_k<<<1, 1024>>>(deg2, rpt2, fil2);
    fill2_k<<<(Nv * Kp + 255) / 256, 256>>>(cooi, cooj, coow, nnz, rpt2, fil2, col2, wcs2);

    // layer-1 propagates (both views), batched W2 GEMM, layer-2 propagates
    prop_k<Dh, 1><<<Nv, Dh>>>(xw1, rptr, csrc, dinv, b1, nullptr, bah, bal);
    spmm_csr_k<1><<<Nv, Dh>>>(rpt2, col2, wcs2, xw1, b1, nullptr, ba2h, ba2l);
    mma_nt_k<false><<<dim3(2, 32, 2), 256, SMEM_DYN>>>(
        bah, bal, ba2h, ba2l, w2th, w2tl, bufB, bufB2, nullptr, nullptr, Dh, Dh, 0);
    prop_k<Dh, 2><<<Nv, Dh>>>(bufB, rptr, csrc, dinv, b2, z1, z1h, z1l);
    spmm_csr_k<2><<<Nv, Dh>>>(rpt2, col2, wcs2, bufB2, b2, z2, z2h, z2l);

    // fused z1n @ z2n^T: row exp-sums + diag
    mma_nt_k<true><<<dim3(32, 32, 1), 256, SMEM_DYN>>>(
        z1h, z1l, nullptr, nullptr, z2h, z2l, nullptr, nullptr, gs, gd, Dh, Nv, 0);

    // pf/pb + loss
    pfpb_k<<<COO_CAP / 8, 256>>>(cooi, cooj, coow, nnz, z1, z2, gs, pf, pb);
    loss_k<<<1, 256>>>(gd, gs, pf, pb, out);
}

// round 7
// speedup vs baseline: 3.3786x; 1.0986x over previous
#include <cuda_runtime.h>
#include <math.h>
#include <stdint.h>

// ---------------- problem constants ----------------
namespace {
constexpr int    Nv   = 4096;
constexpr int    Din  = 128;
constexpr int    Dh   = 256;
constexpr int    Kp   = 17;          // K+1
constexpr float  Eps  = 1e-8f;
constexpr float  InvT = 5.0f;        // 1/TEMP
constexpr size_t NN   = (size_t)Nv * (size_t)Nv;
constexpr int    Emax = 131072;
constexpr int    COO_CAP = 131072;
constexpr int    HCAP = 1 << 18;
constexpr int    CSR2_CAP = 160000;

// scratch heap layout (units: floats)
constexpr size_t O_SIM  = 0;
constexpr size_t O_X1   = O_SIM + NN;
constexpr size_t O_AGG  = O_X1  + (size_t)Nv*Din;
constexpr size_t O_HN   = O_AGG + (size_t)Nv*Din;
constexpr size_t O_XW1  = O_HN  + (size_t)Nv*Dh;
constexpr size_t O_H1   = O_XW1 + (size_t)Nv*Dh;
constexpr size_t O_G1   = O_H1  + (size_t)Nv*Dh;
constexpr size_t O_BUFB = O_G1  + (size_t)Nv*Dh;
constexpr size_t O_BUFB2= O_BUFB+ (size_t)Nv*Dh;
constexpr size_t O_Z1   = O_BUFB2+(size_t)Nv*Dh;
constexpr size_t O_Z2   = O_Z1  + (size_t)Nv*Dh;
constexpr size_t O_W1T  = O_Z2  + (size_t)Nv*Dh;       // [Dh][Din]
constexpr size_t O_W2T  = O_W1T + (size_t)Dh*Din;      // [Dh][Dh]
constexpr size_t O_DEG  = O_W2T + (size_t)Dh*Dh;
constexpr size_t O_DINV = O_DEG + Nv;
constexpr size_t O_GS   = O_DINV+ Nv;
constexpr size_t O_PF   = O_GS  + Nv;
constexpr size_t O_PB   = O_PF  + Nv;
constexpr size_t O_GD   = O_PB  + Nv;
constexpr size_t O_RPTR = O_GD  + Nv;
constexpr size_t O_FILL = O_RPTR+ (Nv + 4);
constexpr size_t O_CSRC = O_FILL+ Nv;
constexpr size_t O_TOPI = O_CSRC+ Emax;
constexpr size_t O_TOPV = O_TOPI+ (size_t)Nv*Kp;
constexpr size_t O_COOI = O_TOPV+ (size_t)Nv*Kp;
constexpr size_t O_COOJ = O_COOI+ COO_CAP;
constexpr size_t O_COOW = O_COOJ+ COO_CAP;
constexpr size_t O_NNZ  = O_COOW+ COO_CAP;
constexpr size_t O_HKEY = O_NNZ + 4;
constexpr size_t O_HSUM = O_HKEY+ HCAP;
constexpr size_t O_HCNT = O_HSUM+ HCAP;
constexpr size_t O_DEG2 = O_HCNT+ HCAP;
constexpr size_t O_RPT2 = O_DEG2+ Nv;
constexpr size_t O_FIL2 = O_RPT2+ (Nv + 4);
constexpr size_t O_COL2 = O_FIL2+ Nv;
constexpr size_t O_WCS2 = O_COL2+ CSR2_CAP;
constexpr size_t TOTAL  = O_WCS2+ CSR2_CAP;

// GEMM smem: 2 stages x 2 arrays x 128 rows x 36 u32 (32 data + 4 pad)
constexpr unsigned SMEM_DYN = (2 * 2 * 4608 + 128) * 4;
}

__device__ __align__(256) float g_heap[TOTAL];

// ---------------- fast exp (FMA only) ----------------
__device__ __forceinline__ float fexp(float x) {
    float t  = x * 1.4426950408889634f;
    float rf = __fadd_rn(t, 12582912.0f);
    int   e  = __float_as_int(rf) - 0x4B400000;
    float r  = __fadd_rn(rf, -12582912.0f);
    float f  = t - r;
    float p  = fmaf(1.5403530394e-4f, f, 1.3333558146e-3f);
    p = fmaf(p, f, 9.6181291076e-3f);
    p = fmaf(p, f, 5.5504108665e-2f);
    p = fmaf(p, f, 2.4022650696e-1f);
    p = fmaf(p, f, 6.9314718056e-1f);
    p = fmaf(p, f, 1.0f);
    return __int_as_float(__float_as_int(p) + (e << 23));
}

// ---------------- tf32 mma helpers (arch-generic, sm_80+) ----------------
__device__ __forceinline__ uint32_t tf32r(uint32_t x) {
    uint32_t r;
    asm("cvt.rna.tf32.f32 %0, %1;" : "=r"(r) : "f"(__uint_as_float(x)));
    return r;
}
__device__ __forceinline__ void mma_tf32(float* c, const uint32_t* a, const uint32_t* b) {
    asm volatile(
        "mma.sync.aligned.m16n8k8.row.col.f32.tf32.tf32.f32 "
        "{%0,%1,%2,%3}, {%4,%5,%6,%7}, {%8,%9}, {%0,%1,%2,%3};"
        : "+f"(c[0]), "+f"(c[1]), "+f"(c[2]), "+f"(c[3])
        : "r"(a[0]), "r"(a[1]), "r"(a[2]), "r"(a[3]), "r"(b[0]), "r"(b[1]));
}
__device__ __forceinline__ uint32_t smem_u32(const void* p) {
    uint32_t a;
    asm("{ .reg .u64 t; cvta.to.shared.u64 t, %1; cvt.u32.u64 %0, t; }" : "=r"(a) : "l"(p));
    return a;
}
__device__ __forceinline__ void cpa16(uint32_t dst, const void* src) {
    asm volatile("cp.async.cg.shared.global [%0], [%1], 16;" :: "r"(dst), "l"(src));
}
#define CP_COMMIT() asm volatile("cp.async.commit_group;" ::: "memory")
#define LDMX4(r0, r1, r2, r3, addr) \
    asm volatile("ldmatrix.sync.aligned.m8n8.x4.shared.b16 {%0,%1,%2,%3}, [%4];" \
        : "=r"(r0), "=r"(r1), "=r"(r2), "=r"(r3) : "r"(addr))

// ---------------- init / small kernels ----------------
__global__ void init_k(float* deg, int* hkey, float* hsum, int* hcnt,
                       int* deg2, int* nnz, float* gs3) {
    int i = blockIdx.x * blockDim.x + threadIdx.x;
    if (i < HCAP) { hkey[i] = -1; hsum[i] = 0.f; hcnt[i] = 0; }
    if (i < Nv) { deg[i] = 1.f; deg2[i] = 0; }
    if (i < Nv * 3) gs3[i] = 0.f;
    if (i == 0) nnz[0] = 0;
}
__global__ void deg_count_k(const int* dst, float* deg, int E) {
    int e = blockIdx.x * blockDim.x + threadIdx.x;
    if (e < E) atomicAdd(&deg[dst[e]], 1.f);
}

__global__ void x1_k(const float* x, const float* pf, const float* ps, float* x1) {
    int i = blockIdx.x * blockDim.x + threadIdx.x;
    if (i >= Nv * Din) return;
    int c = i % Din;
    float v = x[i] * pf[c];
    x1[i] = fmaxf(v, 0.f) * ps[c];
}

__global__ void transpose_k(const float* __restrict__ A, float* __restrict__ AT,
                            int R, int Cc) {
    __shared__ float tile[32][33];
    int x = blockIdx.x * 32 + threadIdx.x;
    int y = blockIdx.y * 32 + threadIdx.y;
    tile[threadIdx.y][threadIdx.x] = A[(size_t)y * Cc + x];
    __syncthreads();
    int xo = blockIdx.y * 32 + threadIdx.x;
    int yo = blockIdx.x * 32 + threadIdx.y;
    AT[(size_t)yo * R + xo] = tile[threadIdx.x][threadIdx.y];
}

// ---------------- CSR build (original graph); dinv fused into scan ----------------
__global__ void scan_k(const float* deg, float* dinv, int* rowptr, int* fill) {
    __shared__ int s[1024];
    int t = threadIdx.x;
    int c[4]; int loc = 0;
    #pragma unroll
    for (int q = 0; q < 4; q++) {
        float d = deg[t * 4 + q];
        dinv[t * 4 + q] = rsqrtf(d);
        c[q] = (int)d - 1; loc += c[q];
    }
    s[t] = loc; __syncthreads();
    for (int off = 1; off < 1024; off <<= 1) {
        int v = (t >= off) ? s[t - off] : 0;
        __syncthreads();
        s[t] += v;
        __syncthreads();
    }
    int run = s[t] - loc;
    #pragma unroll
    for (int q = 0; q < 4; q++) {
        rowptr[t * 4 + q] = run; run += c[q];
        fill[t * 4 + q] = 0;
    }
    if (t == 1023) rowptr[Nv] = run;
}

__global__ void fill_k(const int* es, const int* ed, const int* rowptr,
                       int* fill, int* csrc, int E) {
    int e = blockIdx.x * blockDim.x + threadIdx.x;
    if (e >= E) return;
    int d = ed[e];
    int p = rowptr[d] + atomicAdd(&fill[d], 1);
    csrc[p] = es[e];
}

// ---------------- CSR gather propagate ----------------
template<int F, int EPI>
__global__ void prop_k(const float* __restrict__ X, const int* __restrict__ rowptr,
                       const int* __restrict__ csrc, const float* __restrict__ dinv,
                       const float* __restrict__ bias, float* __restrict__ out) {
    __shared__ int   sI[F];
    __shared__ float sW[F];
    __shared__ float red[(EPI == 2) ? F : 1];
    int r = blockIdx.x, t = threadIdx.x;
    int beg = rowptr[r], end = rowptr[r + 1];
    float acc = 0.f;
    for (int base = beg; base < end; base += F) {
        int m = min(F, end - base);
        if (t < m) { int s = csrc[base + t]; sI[t] = s; sW[t] = dinv[s]; }
        __syncthreads();
        #pragma unroll 4
        for (int q = 0; q < m; q++) acc += sW[q] * X[(size_t)sI[q] * F + t];
        __syncthreads();
    }
    float dv = dinv[r];
    float v = dv * dv * X[(size_t)r * F + t] + dv * acc;
    if (EPI == 0) {
        out[(size_t)r * F + t] = v;
    } else if (EPI == 1) {
        out[(size_t)r * F + t] = fmaxf(v + bias[t], 0.f);
    } else {
        v += bias[t];
        v = v > 0.f ? v : expm1f(v);
        red[t] = v * v; __syncthreads();
        for (int s = F / 2; s > 0; s >>= 1) { if (t < s) red[t] += red[t + s]; __syncthreads(); }
        out[(size_t)r * F + t] = v / (sqrtf(red[0]) + Eps);
    }
}

__global__ void hn_k(const float* x1, const float* agg, const float* pbal, float* hn) {
    __shared__ float sh[256];
    int r = blockIdx.x, t = threadIdx.x;
    float v = (t < Din ? x1[(size_t)r * Din + t] : agg[(size_t)r * Din + (t - Din)]) * pbal[t];
    sh[t] = v * v; __syncthreads();
    for (int s = 128; s > 0; s >>= 1) { if (t < s) sh[t] += sh[t + s]; __syncthreads(); }
    hn[(size_t)r * Dh + t] = v / (sqrtf(sh[0]) + Eps);
}

// ---------------- NT GEMM: single-pass TF32 mma, cp.async double buffer ----------------
// C[M,Nc] = A[M,Kk] * B[Nc,Kk]^T (fp32 in, tf32 compute, fp32 acc).
// grid (Nc/128, M/128, batch); z==1 -> A2/C2.
template<bool FUSE>
__global__ __launch_bounds__(256)
void mma_nt_k(const float* __restrict__ A, const float* __restrict__ A2,
              const float* __restrict__ B,
              float* C, float* C2, float* __restrict__ gs, float* __restrict__ gdiag,
              int Kk, int Nc, int sym) {
    extern __shared__ uint32_t dsm[];
    float* rowsum = (float*)(dsm + 2 * 2 * 4608);

    int bx = blockIdx.x, by = blockIdx.y;
    if (sym && by > bx) return;
    if (blockIdx.z == 1) { A = A2; C = C2; }
    int brow = by * 128, bcol = bx * 128;
    int tid = threadIdx.x;
    int lane = tid & 31, wid = tid >> 5;
    int g = lane >> 2, tg = lane & 3;
    int lrow = lane & 7, lhalf = (lane >> 3) & 1, lcol = lane >> 4;
    int wm = (wid >> 1) * 32, wn = (wid & 1) * 64;
    int nch = Kk >> 5;
    uint32_t smb = smem_u32(dsm);

    auto issue = [&](int st, int c) {
        #pragma unroll
        for (int l = 0; l < 8; l++) {
            int id = l * 256 + tid;
            int arr = id >> 10;               // 0:A 1:B
            int rem = id & 1023;
            int row = rem >> 3, seg = rem & 7;
            const float* gp = arr ? B : A;
            int rb = arr ? bcol : brow;
            const float* src = gp + (size_t)(rb + row) * Kk + c * 32 + seg * 4;
            uint32_t dst = smb + ((st * 2 + arr) * 4608 + row * 36 + seg * 4) * 4;
            cpa16(dst, src);
        }
        CP_COMMIT();
    };

    float acc[2][8][4];
    #pragma unroll
    for (int mt = 0; mt < 2; mt++)
        #pragma unroll
        for (int nt = 0; nt < 8; nt++)
            #pragma unroll
            for (int q = 0; q < 4; q++) acc[mt][nt][q] = 0.f;

    issue(0, 0);
    issue(1, 1);

    for (int c = 0; c < nch; c++) {
        if (c + 1 < nch) asm volatile("cp.async.wait_group 1;" ::: "memory");
        else             asm volatile("cp.async.wait_group 0;" ::: "memory");
        __syncthreads();
        int st = c & 1;
        uint32_t bA = smb + (st * 2 + 0) * 18432;
        uint32_t bB = smb + (st * 2 + 1) * 18432;
        #pragma unroll
        for (int k8 = 0; k8 < 4; k8++) {
            int cb = k8 * 8 + lcol * 4;
            uint32_t af[2][4];
            #pragma unroll
            for (int mt = 0; mt < 2; mt++) {
                uint32_t off = bA + ((wm + mt * 16 + lrow + lhalf * 8) * 36 + cb) * 4;
                LDMX4(af[mt][0], af[mt][1], af[mt][2], af[mt][3], off);
                af[mt][0] = tf32r(af[mt][0]); af[mt][1] = tf32r(af[mt][1]);
                af[mt][2] = tf32r(af[mt][2]); af[mt][3] = tf32r(af[mt][3]);
            }
            uint32_t bf[8][2];
            #pragma unroll
            for (int np = 0; np < 4; np++) {
                uint32_t off = bB + ((wn + np * 16 + lrow + lhalf * 8) * 36 + cb) * 4;
                uint32_t t0, t1, t2, t3;
                LDMX4(t0, t1, t2, t3, off);
                bf[np * 2][0]     = tf32r(t0); bf[np * 2][1]     = tf32r(t2);
                bf[np * 2 + 1][0] = tf32r(t1); bf[np * 2 + 1][1] = tf32r(t3);
            }
            #pragma unroll
            for (int mt = 0; mt < 2; mt++)
                #pragma unroll
                for (int nt = 0; nt < 8; nt++)
                    mma_tf32(acc[mt][nt], af[mt], bf[nt]);
        }
        __syncthreads();
        if (c + 2 < nch) issue(st, c + 2);
    }

    if (!FUSE) {
        #pragma unroll
        for (int mt = 0; mt < 2; mt++)
            #pragma unroll
            for (int nt = 0; nt < 8; nt++) {
                int r0 = brow + wm + mt * 16 + g;
                int c0 = bcol + wn + nt * 8 + 2 * tg;
                *(float2*)(C + (size_t)r0 * Nc + c0)       = make_float2(acc[mt][nt][0], acc[mt][nt][1]);
                *(float2*)(C + (size_t)(r0 + 8) * Nc + c0) = make_float2(acc[mt][nt][2], acc[mt][nt][3]);
            }
        if (sym && bx != by) {
            float (*Tb)[130] = (float(*)[130])dsm;    // 64 x 130 staging
            #pragma unroll
            for (int h = 0; h < 2; h++) {
                __syncthreads();
                if ((wid & 1) == h) {
                    #pragma unroll
                    for (int mt = 0; mt < 2; mt++)
                        #pragma unroll
                        for (int nt = 0; nt < 8; nt++) {
                            int rr = wm + mt * 16 + g;
                            int cl = nt * 8 + 2 * tg;
                            Tb[cl][rr]         = acc[mt][nt][0];
                            Tb[cl + 1][rr]     = acc[mt][nt][1];
                            Tb[cl][rr + 8]     = acc[mt][nt][2];
                            Tb[cl + 1][rr + 8] = acc[mt][nt][3];
                        }
                }
                __syncthreads();
                #pragma unroll
                for (int it = 0; it < 8; it++) {
                    int idx = tid + it * 256;
                    int rloc = idx >> 5, q = idx & 31;
                    float4 v = make_float4(Tb[rloc][4 * q], Tb[rloc][4 * q + 1],
                                           Tb[rloc][4 * q + 2], Tb[rloc][4 * q + 3]);
                    *(float4*)(C + (size_t)(bcol + h * 64 + rloc) * Nc + brow + 4 * q) = v;
                }
            }
        }
    } else {
        if (tid < 128) rowsum[tid] = 0.f;
        __syncthreads();
        #pragma unroll
        for (int mt = 0; mt < 2; mt++) {
            int lr0 = wm + mt * 16 + g;
            int gr0 = brow + lr0;
            float rs0 = 0.f, rs1 = 0.f;
            #pragma unroll
            for (int nt = 0; nt < 8; nt++) {
                int gc = bcol + wn + nt * 8 + 2 * tg;
                float e0 = fexp(InvT * acc[mt][nt][0]);
                float e1 = fexp(InvT * acc[mt][nt][1]);
                float e2 = fexp(InvT * acc[mt][nt][2]);
                float e3 = fexp(InvT * acc[mt][nt][3]);
                rs0 += e0 + e1;
                rs1 += e2 + e3;
                if (gc == gr0)         gdiag[gr0] = e0;
                if (gc + 1 == gr0)     gdiag[gr0] = e1;
                if (gc == gr0 + 8)     gdiag[gr0 + 8] = e2;
                if (gc + 1 == gr0 + 8) gdiag[gr0 + 8] = e3;
            }
            rs0 += __shfl_xor_sync(0xffffffffu, rs0, 1);
            rs0 += __shfl_xor_sync(0xffffffffu, rs0, 2);
            rs1 += __shfl_xor_sync(0xffffffffu, rs1, 1);
            rs1 += __shfl_xor_sync(0xffffffffu, rs1, 2);
            if (tg == 0) {
                atomicAdd(&rowsum[lr0], rs0);
                atomicAdd(&rowsum[lr0 + 8], rs1);
            }
        }
        __syncthreads();
        if (tid < 128) atomicAdd(&gs[brow + tid], rowsum[tid]);
    }
}

// ---------------- top-k (iterative argmax with cached local maxima) ----------------
__global__ void topk_k(const float* __restrict__ sim, int* topi, float* topv) {
    __shared__ float sv[Nv];
    __shared__ float lv[256];
    __shared__ int   li[256];
    __shared__ float wv[8];
    __shared__ int   wi[8];
    int r = blockIdx.x, t = threadIdx.x;
    float best = -1e30f; int besti = 1 << 30;
    #pragma unroll
    for (int q = 0; q < 16; q++) {
        int i = t + q * 256;
        float v = sim[(size_t)r * Nv + i];
        sv[i] = v;
        if (v > best) { best = v; besti = i; }
    }
    lv[t] = best; li[t] = besti;
    __syncthreads();
    for (int k = 0; k < Kp; k++) {
        float b = lv[t]; int bi = li[t];
        #pragma unroll
        for (int o = 16; o > 0; o >>= 1) {
            float ov = __shfl_down_sync(0xffffffffu, b, o);
            int   oi = __shfl_down_sync(0xffffffffu, bi, o);
            if (ov > b || (ov == b && oi < bi)) { b = ov; bi = oi; }
        }
        if ((t & 31) == 0) { wv[t >> 5] = b; wi[t >> 5] = bi; }
        __syncthreads();
        if (t == 0) {
            float bb = wv[0]; int bj = wi[0];
            #pragma unroll
            for (int w = 1; w < 8; w++)
                if (wv[w] > bb || (wv[w] == bb && wi[w] < bj)) { bb = wv[w]; bj = wi[w]; }
            topv[r * Kp + k] = bb;
            topi[r * Kp + k] = bj;
            sv[bj] = -1e30f;
            wi[0] = bj;
        }
        __syncthreads();
        int bj = wi[0];
        if ((bj & 255) == t) {
            float nb = -1e30f; int ni = 1 << 30;
            #pragma unroll
            for (int q = 0; q < 16; q++) {
                int i = t + q * 256;
                float v = sv[i];
                if (v > nb) { nb = v; ni = i; }
            }
            lv[t] = nb; li[t] = ni;
        }
        __syncthreads();
    }
}

// ---------------- hash-based symmetric Wund ----------------
__global__ void hash_ins_k(const int* ti, const float* tv,
                           int* hkey, float* hsum, int* hcnt) {
    int e = blockIdx.x * blockDim.x + threadIdx.x;
    if (e >= Nv * Kp) return;
    int r = e / Kp, c = ti[e];
    float v = tv[e];
    if (v != v) v = 0.f;
    int i = min(r, c), j = max(r, c);
    int key = (i << 12) | j;
    uint32_t slot = ((uint32_t)key * 2654435761u) >> 14;
    slot &= (HCAP - 1);
    while (true) {
        int old = atomicCAS(&hkey[slot], -1, key);
        if (old == -1 || old == key) break;
        slot = (slot + 1) & (HCAP - 1);
    }
    atomicAdd(&hsum[slot], v);
    atomicAdd(&hcnt[slot], 1);
}

__global__ void hash_emit_k(const int* hkey, const float* hsum, const int* hcnt,
                            int* cooi, int* cooj, float* coow, int* nnz, int* deg2) {
    int s = blockIdx.x * blockDim.x + threadIdx.x;
    if (s >= HCAP) return;
    int key = hkey[s];
    if (key < 0) return;
    float o = hsum[s] / (float)hcnt[s];
    if (o <= 0.f) return;
    int i = key >> 12, j = key & 4095;
    int p = atomicAdd(nnz, 1);
    cooi[p] = i; cooj[p] = j; coow[p] = o;
    atomicAdd(&deg2[i], 1);
    if (i != j) atomicAdd(&deg2[j], 1);
}

__global__ void scan2_k(const int* deg2, int* rowptr, int* fill) {
    __shared__ int s[1024];
    int t = threadIdx.x;
    int c[4]; int loc = 0;
    #pragma unroll
    for (int q = 0; q < 4; q++) { c[q] = deg2[t * 4 + q]; loc += c[q]; }
    s[t] = loc; __syncthreads();
    for (int off = 1; off < 1024; off <<= 1) {
        int v = (t >= off) ? s[t - off] : 0;
        __syncthreads();
        s[t] += v;
        __syncthreads();
    }
    int run = s[t] - loc;
    #pragma unroll
    for (int q = 0; q < 4; q++) {
        rowptr[t * 4 + q] = run; run += c[q];
        fill[t * 4 + q] = 0;
    }
    if (t == 1023) rowptr[Nv] = run;
}

__global__ void fill2_k(const int* cooi, const int* cooj, const float* coow,
                        const int* nnz, const int* rowptr, int* fill,
                        int* col2, float* w2) {
    int e = blockIdx.x * blockDim.x + threadIdx.x;
    if (e >= *nnz) return;
    int i = cooi[e], j = cooj[e];
    float o = coow[e];
    int p = rowptr[i] + atomicAdd(&fill[i], 1);
    col2[p] = j; w2[p] = o;
    if (i != j) {
        p = rowptr[j] + atomicAdd(&fill[j], 1);
        col2[p] = i; w2[p] = o;
    }
}

// ---------------- CSR SpMM for Wund ----------------
template<int EPI>
__global__ void spmm_csr_k(const int* __restrict__ rowptr, const int* __restrict__ col2,
                           const float* __restrict__ w2, const float* __restrict__ X,
                           const float* __restrict__ bias, float* __restrict__ out) {
    __shared__ int   sI[256];
    __shared__ float sW[256];
    __shared__ float red[256];
    int r = blockIdx.x, t = threadIdx.x;
    int beg = rowptr[r], end = rowptr[r + 1];
    float acc = 0.f;
    for (int base = beg; base < end; base += 256) {
        int m = min(256, end - base);
        if (t < m) { sI[t] = col2[base + t]; sW[t] = w2[base + t]; }
        __syncthreads();
        #pragma unroll 4
        for (int q = 0; q < m; q++) acc += sW[q] * X[(size_t)sI[q] * Dh + t];
        __syncthreads();
    }
    float v = acc + bias[t];
    if (EPI == 1) {
        out[(size_t)r * Dh + t] = fmaxf(v, 0.f);
    } else {
        v = v > 0.f ? v : expm1f(v);
        red[t] = v * v; __syncthreads();
        for (int s = 128; s > 0; s >>= 1) { if (t < s) red[t] += red[t + s]; __syncthreads(); }
        out[(size_t)r * Dh + t] = v / (sqrtf(red[0]) + Eps);
    }
}

// ---------------- pf/pb over COO nonzeros ----------------
__global__ void pfpb_k(const int* coo_i, const int* coo_j, const float* coo_w,
                       const int* nnz, const float* __restrict__ z1,
                       const float* __restrict__ z2, const float* gs,
                       float* pf, float* pb) {
    int wid = (blockIdx.x * blockDim.x + threadIdx.x) >> 5;
    int lane = threadIdx.x & 31;
    if (wid >= *nnz) return;
    int i = coo_i[wid], j = coo_j[wid];
    float wt = coo_w[wid];
    float d1 = 0.f, d2 = 0.f;
    #pragma unroll
    for (int q = 0; q < 8; q++) {
        int c = lane + q * 32;
        d1 += z1[(size_t)i * Dh + c] * z2[(size_t)j * Dh + c];
    }
    if (i != j) {
        #pragma unroll
        for (int q = 0; q < 8; q++) {
            int c = lane + q * 32;
            d2 += z1[(size_t)j * Dh + c] * z2[(size_t)i * Dh + c];
        }
    }
    #pragma unroll
    for (int o = 16; o > 0; o >>= 1) {
        d1 += __shfl_xor_sync(0xffffffffu, d1, o);
        d2 += __shfl_xor_sync(0xffffffffu, d2, o);
    }
    if (lane == 0) {
        float q1 = fexp(InvT * d1) / gs[i] * wt;
        atomicAdd(&pf[i], q1);
        atomicAdd(&pb[j], q1);
        if (i != j) {
            float q2 = fexp(InvT * d2) / gs[j] * wt;
            atomicAdd(&pf[j], q2);
            atomicAdd(&pb[i], q2);
        }
    }
}

__global__ void loss_k(const float* gdiag, const float* gs,
                       const float* pf, const float* pb, float* out) {
    __shared__ float s1[256], s2[256], s3[256];
    int t = threadIdx.x;
    float a = 0.f, b = 0.f, c = 0.f;
    for (int i = t; i < Nv; i += 256) {
        a -= logf(fmaxf(gdiag[i] / gs[i], Eps));
        b -= logf(fmaxf(pf[i], Eps));
        c -= logf(fmaxf(pb[i], Eps));
    }
    s1[t] = a; s2[t] = b; s3[t] = c; __syncthreads();
    for (int st = 128; st > 0; st >>= 1) {
        if (t < st) { s1[t] += s1[t + st]; s2[t] += s2[t + st]; s3[t] += s3[t + st]; }
        __syncthreads();
    }
    if (t == 0) out[0] = s1[0] / Nv + 0.5f * (s2[0] / Nv + s3[0] / Nv);
}

// ---------------- host launcher ----------------
extern "C" void kernel_launch(void* const* d_in, const int* in_sizes, int n_in,
                              void* d_out, int out_size) {
    const float* x       = (const float*)d_in[0];
    const int*   esrc    = (const int*)d_in[1];
    const int*   edst    = (const int*)d_in[2];
    const float* p_feat  = (const float*)d_in[3];
    const float* p_share = (const float*)d_in[4];
    const float* p_bal   = (const float*)d_in[5];
    const float* W1      = (const float*)d_in[6];
    const float* b1      = (const float*)d_in[7];
    const float* W2      = (const float*)d_in[8];
    const float* b2      = (const float*)d_in[9];
    float* out = (float*)d_out;
    int E = in_sizes[1];

    float* H = nullptr;
    cudaGetSymbolAddress((void**)&H, g_heap);
    float* sim  = H + O_SIM;
    float* x1   = H + O_X1;   float* agg  = H + O_AGG;  float* hn  = H + O_HN;
    float* xw1  = H + O_XW1;  float* h1   = H + O_H1;   float* g1  = H + O_G1;
    float* bufB = H + O_BUFB; float* bufB2 = H + O_BUFB2;
    float* z1   = H + O_Z1;   float* z2   = H + O_Z2;
    float* w1t  = H + O_W1T;  float* w2t  = H + O_W2T;
    float* deg  = H + O_DEG;  float* dinv = H + O_DINV;
    float* gs   = H + O_GS;   float* pf   = H + O_PF;   float* pb  = H + O_PB;
    float* gd   = H + O_GD;
    int*   rptr = (int*)(H + O_RPTR);
    int*   fill = (int*)(H + O_FILL);
    int*   csrc = (int*)(H + O_CSRC);
    int*   topi = (int*)(H + O_TOPI);
    float* topv = H + O_TOPV;
    int*   cooi = (int*)(H + O_COOI);
    int*   cooj = (int*)(H + O_COOJ);
    float* coow = H + O_COOW;
    int*   nnz  = (int*)(H + O_NNZ);
    int*   hkey = (int*)(H + O_HKEY);
    float* hsum = H + O_HSUM;
    int*   hcnt = (int*)(H + O_HCNT);
    int*   deg2 = (int*)(H + O_DEG2);
    int*   rpt2 = (int*)(H + O_RPT2);
    int*   fil2 = (int*)(H + O_FIL2);
    int*   col2 = (int*)(H + O_COL2);
    float* wcs2 = H + O_WCS2;

    cudaFuncSetAttribute(mma_nt_k<false>, cudaFuncAttributeMaxDynamicSharedMemorySize, SMEM_DYN);
    cudaFuncSetAttribute(mma_nt_k<true>,  cudaFuncAttributeMaxDynamicSharedMemorySize, SMEM_DYN);

    // init + CSR (original graph) + transposed weights
    init_k<<<HCAP / 256, 256>>>(deg, hkey, hsum, hcnt, deg2, nnz, gs);
    deg_count_k<<<(E + 255) / 256, 256>>>(edst, deg, E);
    scan_k<<<1, 1024>>>(deg, dinv, rptr, fill);
    fill_k<<<(E + 255) / 256, 256>>>(esrc, edst, rptr, fill, csrc, E);
    transpose_k<<<dim3(Dh / 32, Din / 32), dim3(32, 32)>>>(W1, w1t, Din, Dh);
    transpose_k<<<dim3(Dh / 32, Dh / 32),  dim3(32, 32)>>>(W2, w2t, Dh, Dh);

    // prompted features, xw1 GEMM, first propagate, hn
    x1_k<<<(Nv * Din) / 256, 256>>>(x, p_feat, p_share, x1);
    mma_nt_k<false><<<dim3(2, 32, 1), 256, SMEM_DYN>>>(
        x1, nullptr, w1t, xw1, nullptr, nullptr, nullptr, Din, Dh, 0);
    prop_k<Din, 0><<<Nv, Din>>>(x1, rptr, csrc, dinv, nullptr, agg);
    hn_k<<<Nv, 256>>>(x1, agg, p_bal, hn);

    // sim = hn @ hn^T (symmetric, tf32)
    mma_nt_k<false><<<dim3(32, 32, 1), 256, SMEM_DYN>>>(
        hn, nullptr, hn, sim, nullptr, nullptr, nullptr, Dh, Nv, 1);

    // top-k -> hash -> CSR2
    topk_k<<<Nv, 256>>>(sim, topi, topv);
    hash_ins_k<<<(Nv * Kp + 255) / 256, 256>>>(topi, topv, hkey, hsum, hcnt);
    hash_emit_k<<<HCAP / 256, 256>>>(hkey, hsum, hcnt, cooi, cooj, coow, nnz, deg2);
    scan2_k<<<1, 1024>>>(deg2, rpt2, fil2);
    fill2_k<<<(Nv * Kp + 255) / 256, 256>>>(cooi, cooj, coow, nnz, rpt2, fil2, col2, wcs2);

    // layer-1 propagates (both views), batched W2 GEMM, layer-2 propagates
    prop_k<Dh, 1><<<Nv, Dh>>>(xw1, rptr, csrc, dinv, b1, h1);
    spmm_csr_k<1><<<Nv, Dh>>>(rpt2, col2, wcs2, xw1, b1, g1);
    mma_nt_k<false><<<dim3(2, 32, 2), 256, SMEM_DYN>>>(
        h1, g1, w2t, bufB, bufB2, nullptr, nullptr, Dh, Dh, 0);
    prop_k<Dh, 2><<<Nv, Dh>>>(bufB, rptr, csrc, dinv, b2, z1);
    spmm_csr_k<2><<<Nv, Dh>>>(rpt2, col2, wcs2, bufB2, b2, z2);

    // fused z1n @ z2n^T: row exp-sums + diag
    mma_nt_k<true><<<dim3(32, 32, 1), 256, SMEM_DYN>>>(
        z1, nullptr, z2, nullptr, nullptr, gs, gd, Dh, Nv, 0);

    // pf/pb + loss
    pfpb_k<<<COO_CAP / 8, 256>>>(cooi, cooj, coow, nnz, z1, z2, gs, pf, pb);
    loss_k<<<1, 256>>>(gd, gs, pf, pb, out);
}